// round 3
// baseline (speedup 1.0000x reference)
#include <cuda_runtime.h>
#include <cuda_fp16.h>
#include <cuda_bf16.h>
#include <stdint.h>

// ---------------------------------------------------------------------------
// out[b,t,u,o] = sum_h tanh(ep[b,t,h] + dp[b,u,h]) * W2[h,o] + b2[o]
//   ep = enc @ W1[:512],  dp = dec @ W1[512:] + b1
// enc (8,256,512) dec (8,64,512) W1 (1024,1024) b1 (1024) W2 (1024,128) b2 (128)
// out (8,256,64,128) fp32.   Base-ISA only (mma.sync); no tcgen05/TMA.
// ---------------------------------------------------------------------------

__device__ float          g_ep[2048 * 1024];          // enc proj fp32
__device__ float          g_dp[512 * 1024];           // dec proj + b1 fp32
__device__ __nv_bfloat16  g_enc_hi[2048 * 512];
__device__ __nv_bfloat16  g_enc_lo[2048 * 512];
__device__ __nv_bfloat16  g_dec_hi[512 * 512];
__device__ __nv_bfloat16  g_dec_lo[512 * 512];
__device__ __nv_bfloat16  g_w1t_hi[2 * 1024 * 512];   // [part][n][k]
__device__ __nv_bfloat16  g_w1t_lo[2 * 1024 * 512];
__device__ __half         g_w2t[128 * 1024];          // [n][k] = W2[k][n]

__device__ __forceinline__ float tanh_fast(float x) {
    float r; asm("tanh.approx.f32 %0, %1;" : "=f"(r) : "f"(x)); return r;
}

// m16n8k16 fp16 in / fp32 accum
__device__ __forceinline__ void mma_f16(float* c, const uint32_t* a, const uint32_t* b) {
    asm volatile("mma.sync.aligned.m16n8k16.row.col.f32.f16.f16.f32 "
        "{%0,%1,%2,%3}, {%4,%5,%6,%7}, {%8,%9}, {%0,%1,%2,%3};"
        : "+f"(c[0]), "+f"(c[1]), "+f"(c[2]), "+f"(c[3])
        : "r"(a[0]), "r"(a[1]), "r"(a[2]), "r"(a[3]), "r"(b[0]), "r"(b[1]));
}
// m16n8k16 bf16 in / fp32 accum
__device__ __forceinline__ void mma_bf16(float* c, const uint32_t* a, const uint32_t* b) {
    asm volatile("mma.sync.aligned.m16n8k16.row.col.f32.bf16.bf16.f32 "
        "{%0,%1,%2,%3}, {%4,%5,%6,%7}, {%8,%9}, {%0,%1,%2,%3};"
        : "+f"(c[0]), "+f"(c[1]), "+f"(c[2]), "+f"(c[3])
        : "r"(a[0]), "r"(a[1]), "r"(a[2]), "r"(a[3]), "r"(b[0]), "r"(b[1]));
}

// ---------------------------------------------------------------------------
// Prep kernels
// ---------------------------------------------------------------------------
__global__ __launch_bounds__(256) void prep_split(const float* __restrict__ enc,
                                                  const float* __restrict__ dec) {
    int i = blockIdx.x * 256 + threadIdx.x;
    if (i < 2048 * 512) {
        float x = enc[i];
        __nv_bfloat16 h = __float2bfloat16(x);
        g_enc_hi[i] = h;
        g_enc_lo[i] = __float2bfloat16(x - __bfloat162float(h));
    }
    if (i < 512 * 512) {
        float x = dec[i];
        __nv_bfloat16 h = __float2bfloat16(x);
        g_dec_hi[i] = h;
        g_dec_lo[i] = __float2bfloat16(x - __bfloat162float(h));
    }
}

__global__ __launch_bounds__(256) void prep_w1t(const float* __restrict__ W1) {
    __shared__ float tile[32][33];
    int tx = threadIdx.x & 31, ty = threadIdx.x >> 5;
    int bx = blockIdx.x & 31;        // n tile
    int by = blockIdx.x >> 5;        // k tile
    #pragma unroll
    for (int r = 0; r < 4; r++)
        tile[ty + r * 8][tx] = W1[(by * 32 + ty + r * 8) * 1024 + bx * 32 + tx];
    __syncthreads();
    #pragma unroll
    for (int r = 0; r < 4; r++) {
        int n  = bx * 32 + ty + r * 8;
        int kk = by * 32 + tx;
        float x = tile[tx][ty + r * 8];
        int p = kk >> 9;
        int idx = (p * 1024 + n) * 512 + (kk & 511);
        __nv_bfloat16 h = __float2bfloat16(x);
        g_w1t_hi[idx] = h;
        g_w1t_lo[idx] = __float2bfloat16(x - __bfloat162float(h));
    }
}

__global__ __launch_bounds__(256) void prep_w2t(const float* __restrict__ W2) {
    __shared__ float tile[32][33];
    int tx = threadIdx.x & 31, ty = threadIdx.x >> 5;
    int bx = blockIdx.x & 3;          // n tile
    int by = blockIdx.x >> 2;         // k tile
    #pragma unroll
    for (int r = 0; r < 4; r++)
        tile[ty + r * 8][tx] = W2[(by * 32 + ty + r * 8) * 128 + bx * 32 + tx];
    __syncthreads();
    #pragma unroll
    for (int r = 0; r < 4; r++) {
        int n = bx * 32 + ty + r * 8;
        int k = by * 32 + tx;
        g_w2t[n * 1024 + k] = __float2half(tile[tx][ty + r * 8]);
    }
}

// ---------------------------------------------------------------------------
// Projection: C[128x128 tile] = A[128x512] @ Wt[128x512]^T  (bf16 hi/lo x3)
// blocks 0..127: enc -> g_ep ; blocks 128..159: dec -> g_dp (+b1)
// KC = 32 per chunk; smem rows padded to 40 bf16 (conflict-free frag loads).
// ---------------------------------------------------------------------------
__global__ __launch_bounds__(256) void proj_kernel(const float* __restrict__ b1) {
    __shared__ __align__(16) __nv_bfloat16 sAH[128][40];
    __shared__ __align__(16) __nv_bfloat16 sAL[128][40];
    __shared__ __align__(16) __nv_bfloat16 sBH[128][40];
    __shared__ __align__(16) __nv_bfloat16 sBL[128][40];

    int tid = threadIdx.x, wid = tid >> 5, lane = tid & 31;
    int gq = lane >> 2, tg = lane & 3;          // groupID, thread-in-group
    int warp_m = wid >> 1, warp_n = wid & 1;    // 4 x 2 warp grid

    int id = blockIdx.x;
    bool isdec = id >= 128;
    int lid2 = isdec ? id - 128 : id;
    int tile_m = lid2 >> 3, tile_n = lid2 & 7;
    int m0 = tile_m * 128, n0 = tile_n * 128;

    const __nv_bfloat16* Ahi = isdec ? g_dec_hi : g_enc_hi;
    const __nv_bfloat16* Alo = isdec ? g_dec_lo : g_enc_lo;
    const __nv_bfloat16* Bhi = g_w1t_hi + (isdec ? 1024 * 512 : 0);
    const __nv_bfloat16* Blo = g_w1t_lo + (isdec ? 1024 * 512 : 0);
    float* Cout = isdec ? g_dp : g_ep;

    float c[2][8][4];
    #pragma unroll
    for (int i = 0; i < 2; i++)
        #pragma unroll
        for (int j = 0; j < 8; j++)
            #pragma unroll
            for (int q = 0; q < 4; q++) c[i][j][q] = 0.f;

    for (int kc = 0; kc < 16; kc++) {
        __syncthreads();
        #pragma unroll
        for (int it = 0; it < 2; it++) {
            int i = tid + it * 256;
            int r = i >> 2, g = i & 3;
            size_t sa = (size_t)(m0 + r) * 512 + kc * 32 + g * 8;
            *(uint4*)&sAH[r][g * 8] = *(const uint4*)(Ahi + sa);
            *(uint4*)&sAL[r][g * 8] = *(const uint4*)(Alo + sa);
            size_t sbx = (size_t)(n0 + r) * 512 + kc * 32 + g * 8;
            *(uint4*)&sBH[r][g * 8] = *(const uint4*)(Bhi + sbx);
            *(uint4*)&sBL[r][g * 8] = *(const uint4*)(Blo + sbx);
        }
        __syncthreads();

        #pragma unroll
        for (int ks = 0; ks < 2; ks++) {
            int kk = ks * 16;
            uint32_t aH[2][4], aL[2][4];
            #pragma unroll
            for (int mt = 0; mt < 2; mt++) {
                int rb = warp_m * 32 + mt * 16;
                aH[mt][0] = *(const uint32_t*)&sAH[rb + gq][kk + tg * 2];
                aH[mt][1] = *(const uint32_t*)&sAH[rb + gq + 8][kk + tg * 2];
                aH[mt][2] = *(const uint32_t*)&sAH[rb + gq][kk + tg * 2 + 8];
                aH[mt][3] = *(const uint32_t*)&sAH[rb + gq + 8][kk + tg * 2 + 8];
                aL[mt][0] = *(const uint32_t*)&sAL[rb + gq][kk + tg * 2];
                aL[mt][1] = *(const uint32_t*)&sAL[rb + gq + 8][kk + tg * 2];
                aL[mt][2] = *(const uint32_t*)&sAL[rb + gq][kk + tg * 2 + 8];
                aL[mt][3] = *(const uint32_t*)&sAL[rb + gq + 8][kk + tg * 2 + 8];
            }
            #pragma unroll
            for (int nb = 0; nb < 8; nb++) {
                int n = warp_n * 64 + nb * 8 + gq;
                uint32_t bH[2], bL[2];
                bH[0] = *(const uint32_t*)&sBH[n][kk + tg * 2];
                bH[1] = *(const uint32_t*)&sBH[n][kk + tg * 2 + 8];
                bL[0] = *(const uint32_t*)&sBL[n][kk + tg * 2];
                bL[1] = *(const uint32_t*)&sBL[n][kk + tg * 2 + 8];
                #pragma unroll
                for (int mt = 0; mt < 2; mt++) {
                    mma_bf16(c[mt][nb], aH[mt], bH);
                    mma_bf16(c[mt][nb], aH[mt], bL);
                    mma_bf16(c[mt][nb], aL[mt], bH);
                }
            }
        }
    }

    // epilogue
    #pragma unroll
    for (int nb = 0; nb < 8; nb++) {
        int col = n0 + warp_n * 64 + nb * 8 + tg * 2;
        float bb0 = 0.f, bb1 = 0.f;
        if (isdec) { bb0 = __ldg(b1 + col); bb1 = __ldg(b1 + col + 1); }
        #pragma unroll
        for (int mt = 0; mt < 2; mt++) {
            int row = m0 + warp_m * 32 + mt * 16 + gq;
            float2 v0 = make_float2(c[mt][nb][0] + bb0, c[mt][nb][1] + bb1);
            float2 v1 = make_float2(c[mt][nb][2] + bb0, c[mt][nb][3] + bb1);
            *(float2*)(Cout + (size_t)row * 1024 + col) = v0;
            *(float2*)(Cout + (size_t)(row + 8) * 1024 + col) = v1;
        }
    }
}

// ---------------------------------------------------------------------------
// Fused kernel: per CTA: batch b, 2 t, 64 u -> M=128 rows (r = t_local*64+u),
// N=128 outputs, K=1024 in 16 chunks of 64. hidden generated on the fly.
// ---------------------------------------------------------------------------
__global__ __launch_bounds__(256) void fused_kernel(float* __restrict__ out,
                                                    const float* __restrict__ b2) {
    __shared__ __align__(16) __half As[128][72];
    __shared__ __align__(16) __half Bs[128][72];

    int tid = threadIdx.x, wid = tid >> 5, lane = tid & 31;
    int gq = lane >> 2, tg = lane & 3;
    int warp_m = wid >> 1, warp_n = wid & 1;

    int b  = blockIdx.x >> 7;
    int tp = blockIdx.x & 127;
    int t0 = tp * 2;

    // A-gen mapping: thread -> (row, half of k-chunk)
    int arow = tid >> 1;
    int k0   = (tid & 1) * 32;
    const float* ep_base = g_ep + (size_t)(b * 256 + t0 + (arow >> 6)) * 1024 + k0;
    const float* dp_base = g_dp + (size_t)(b * 64 + (arow & 63)) * 1024 + k0;

    float c[2][8][4];
    #pragma unroll
    for (int i = 0; i < 2; i++)
        #pragma unroll
        for (int j = 0; j < 8; j++)
            #pragma unroll
            for (int q = 0; q < 4; q++) c[i][j][q] = 0.f;

    for (int kc = 0; kc < 16; kc++) {
        __syncthreads();
        // stage W2^T tile (128 x 64 fp16)
        #pragma unroll
        for (int it = 0; it < 4; it++) {
            int i = tid + it * 256;
            int n = i >> 3, g = i & 7;
            *(uint4*)&Bs[n][g * 8] =
                *(const uint4*)(g_w2t + (size_t)n * 1024 + kc * 64 + g * 8);
        }
        // generate A = tanh(ep + dp) fp16 (each thread: 1 row, 32 k)
        {
            const float* eprow = ep_base + kc * 64;
            const float* dprow = dp_base + kc * 64;
            #pragma unroll
            for (int q = 0; q < 4; q++) {
                float4 e0 = *(const float4*)(eprow + q * 8);
                float4 e1 = *(const float4*)(eprow + q * 8 + 4);
                float4 d0 = *(const float4*)(dprow + q * 8);
                float4 d1 = *(const float4*)(dprow + q * 8 + 4);
                __half2 h0 = __floats2half2_rn(tanh_fast(e0.x + d0.x), tanh_fast(e0.y + d0.y));
                __half2 h1 = __floats2half2_rn(tanh_fast(e0.z + d0.z), tanh_fast(e0.w + d0.w));
                __half2 h2 = __floats2half2_rn(tanh_fast(e1.x + d1.x), tanh_fast(e1.y + d1.y));
                __half2 h3 = __floats2half2_rn(tanh_fast(e1.z + d1.z), tanh_fast(e1.w + d1.w));
                uint4 v = make_uint4(*(uint32_t*)&h0, *(uint32_t*)&h1,
                                     *(uint32_t*)&h2, *(uint32_t*)&h3);
                *(uint4*)&As[arow][k0 + q * 8] = v;
            }
        }
        __syncthreads();

        // consume: 4 k-steps of 16
        #pragma unroll
        for (int ks = 0; ks < 4; ks++) {
            int kk = ks * 16;
            uint32_t aF[2][4];
            #pragma unroll
            for (int mt = 0; mt < 2; mt++) {
                int rb = warp_m * 32 + mt * 16;
                aF[mt][0] = *(const uint32_t*)&As[rb + gq][kk + tg * 2];
                aF[mt][1] = *(const uint32_t*)&As[rb + gq + 8][kk + tg * 2];
                aF[mt][2] = *(const uint32_t*)&As[rb + gq][kk + tg * 2 + 8];
                aF[mt][3] = *(const uint32_t*)&As[rb + gq + 8][kk + tg * 2 + 8];
            }
            #pragma unroll
            for (int nb = 0; nb < 8; nb++) {
                int n = warp_n * 64 + nb * 8 + gq;
                uint32_t bF[2];
                bF[0] = *(const uint32_t*)&Bs[n][kk + tg * 2];
                bF[1] = *(const uint32_t*)&Bs[n][kk + tg * 2 + 8];
                mma_f16(c[0][nb], aF[0], bF);
                mma_f16(c[1][nb], aF[1], bF);
            }
        }
    }

    // epilogue: out row index = b*16384 + t0*64 + r  (contiguous in r)
    size_t orow0 = (size_t)b * 16384 + (size_t)t0 * 64;
    #pragma unroll
    for (int nb = 0; nb < 8; nb++) {
        int col = warp_n * 64 + nb * 8 + tg * 2;
        float bb0 = __ldg(b2 + col);
        float bb1 = __ldg(b2 + col + 1);
        #pragma unroll
        for (int mt = 0; mt < 2; mt++) {
            int row = warp_m * 32 + mt * 16 + gq;
            float2 v0 = make_float2(c[mt][nb][0] + bb0, c[mt][nb][1] + bb1);
            float2 v1 = make_float2(c[mt][nb][2] + bb0, c[mt][nb][3] + bb1);
            *(float2*)(out + (orow0 + row) * 128 + col) = v0;
            *(float2*)(out + (orow0 + row + 8) * 128 + col) = v1;
        }
    }
}

// ---------------------------------------------------------------------------
extern "C" void kernel_launch(void* const* d_in, const int* in_sizes, int n_in,
                              void* d_out, int out_size) {
    const float* enc = (const float*)d_in[0];
    const float* dec = (const float*)d_in[1];
    const float* W1  = (const float*)d_in[2];
    const float* b1  = (const float*)d_in[3];
    const float* W2  = (const float*)d_in[4];
    const float* b2  = (const float*)d_in[5];
    float* out = (float*)d_out;

    prep_split<<<4096, 256>>>(enc, dec);
    prep_w1t<<<1024, 256>>>(W1);
    prep_w2t<<<128, 256>>>(W2);
    proj_kernel<<<160, 256>>>(b1);
    fused_kernel<<<1024, 256>>>(out, b2);
}

// round 4
// speedup vs baseline: 1.2338x; 1.2338x over previous
#include <cuda_runtime.h>
#include <cuda_fp16.h>
#include <cuda_bf16.h>
#include <stdint.h>

// ---------------------------------------------------------------------------
// out[b,t,u,o] = sum_h tanh(ep[b,t,h] + dp[b,u,h]) * W2[h,o] + b2[o]
//   ep = enc @ W1[:512],  dp = dec @ W1[512:] + b1
// enc (8,256,512) dec (8,64,512) W1 (1024,1024) b1 (1024) W2 (1024,128) b2 (128)
// out (8,256,64,128) fp32.   Base-ISA only (mma.sync); no tcgen05/TMA on this build.
// ---------------------------------------------------------------------------

__device__ float          g_ep[2048 * 1024];          // enc proj fp32
__device__ float          g_dp[512 * 1024];           // dec proj + b1 fp32
__device__ __nv_bfloat16  g_enc_hi[2048 * 512];
__device__ __nv_bfloat16  g_enc_lo[2048 * 512];
__device__ __nv_bfloat16  g_dec_hi[512 * 512];
__device__ __nv_bfloat16  g_dec_lo[512 * 512];
__device__ __nv_bfloat16  g_w1t_hi[2 * 1024 * 512];   // [part][n][k]
__device__ __nv_bfloat16  g_w1t_lo[2 * 1024 * 512];
__device__ __half         g_w2t[128 * 1024];          // [n][k] = W2[k][n]

__device__ __forceinline__ uint32_t tanh2_fast(uint32_t x2) {   // half2 tanh
    uint32_t r; asm("tanh.approx.f16x2 %0, %1;" : "=r"(r) : "r"(x2)); return r;
}

// m16n8k16 fp16 in / fp32 accum
__device__ __forceinline__ void mma_f16(float* c, const uint32_t* a, const uint32_t* b) {
    asm volatile("mma.sync.aligned.m16n8k16.row.col.f32.f16.f16.f32 "
        "{%0,%1,%2,%3}, {%4,%5,%6,%7}, {%8,%9}, {%0,%1,%2,%3};"
        : "+f"(c[0]), "+f"(c[1]), "+f"(c[2]), "+f"(c[3])
        : "r"(a[0]), "r"(a[1]), "r"(a[2]), "r"(a[3]), "r"(b[0]), "r"(b[1]));
}
// m16n8k16 bf16 in / fp32 accum
__device__ __forceinline__ void mma_bf16(float* c, const uint32_t* a, const uint32_t* b) {
    asm volatile("mma.sync.aligned.m16n8k16.row.col.f32.bf16.bf16.f32 "
        "{%0,%1,%2,%3}, {%4,%5,%6,%7}, {%8,%9}, {%0,%1,%2,%3};"
        : "+f"(c[0]), "+f"(c[1]), "+f"(c[2]), "+f"(c[3])
        : "r"(a[0]), "r"(a[1]), "r"(a[2]), "r"(a[3]), "r"(b[0]), "r"(b[1]));
}

// ---------------------------------------------------------------------------
// Prep kernels
// ---------------------------------------------------------------------------
__global__ __launch_bounds__(256) void prep_split(const float* __restrict__ enc,
                                                  const float* __restrict__ dec) {
    int i = blockIdx.x * 256 + threadIdx.x;
    if (i < 2048 * 512) {
        float x = enc[i];
        __nv_bfloat16 h = __float2bfloat16(x);
        g_enc_hi[i] = h;
        g_enc_lo[i] = __float2bfloat16(x - __bfloat162float(h));
    }
    if (i < 512 * 512) {
        float x = dec[i];
        __nv_bfloat16 h = __float2bfloat16(x);
        g_dec_hi[i] = h;
        g_dec_lo[i] = __float2bfloat16(x - __bfloat162float(h));
    }
}

__global__ __launch_bounds__(256) void prep_w1t(const float* __restrict__ W1) {
    __shared__ float tile[32][33];
    int tx = threadIdx.x & 31, ty = threadIdx.x >> 5;
    int bx = blockIdx.x & 31;        // n tile
    int by = blockIdx.x >> 5;        // k tile
    #pragma unroll
    for (int r = 0; r < 4; r++)
        tile[ty + r * 8][tx] = W1[(by * 32 + ty + r * 8) * 1024 + bx * 32 + tx];
    __syncthreads();
    #pragma unroll
    for (int r = 0; r < 4; r++) {
        int n  = bx * 32 + ty + r * 8;
        int kk = by * 32 + tx;
        float x = tile[tx][ty + r * 8];
        int p = kk >> 9;
        int idx = (p * 1024 + n) * 512 + (kk & 511);
        __nv_bfloat16 h = __float2bfloat16(x);
        g_w1t_hi[idx] = h;
        g_w1t_lo[idx] = __float2bfloat16(x - __bfloat162float(h));
    }
}

__global__ __launch_bounds__(256) void prep_w2t(const float* __restrict__ W2) {
    __shared__ float tile[32][33];
    int tx = threadIdx.x & 31, ty = threadIdx.x >> 5;
    int bx = blockIdx.x & 3;          // n tile
    int by = blockIdx.x >> 2;         // k tile
    #pragma unroll
    for (int r = 0; r < 4; r++)
        tile[ty + r * 8][tx] = W2[(by * 32 + ty + r * 8) * 128 + bx * 32 + tx];
    __syncthreads();
    #pragma unroll
    for (int r = 0; r < 4; r++) {
        int n = bx * 32 + ty + r * 8;
        int k = by * 32 + tx;
        g_w2t[n * 1024 + k] = __float2half(tile[tx][ty + r * 8]);
    }
}

// ---------------------------------------------------------------------------
// Projection: C tile [128 x 64] = A[128x512] @ Wt[64x512]^T  (bf16 hi/lo x3)
// 320 CTAs: 0..255 enc (16m x 16n), 256..319 dec (4m x 16n, +b1).
// Warp grid 8x1: warp w -> rows w*16..w*16+15, all 64 cols. occ 2.
// ---------------------------------------------------------------------------
__global__ __launch_bounds__(256, 2) void proj_kernel(const float* __restrict__ b1) {
    __shared__ __align__(16) __nv_bfloat16 sAH[128][40];
    __shared__ __align__(16) __nv_bfloat16 sAL[128][40];
    __shared__ __align__(16) __nv_bfloat16 sBH[64][40];
    __shared__ __align__(16) __nv_bfloat16 sBL[64][40];

    int tid = threadIdx.x, wid = tid >> 5, lane = tid & 31;
    int gq = lane >> 2, tg = lane & 3;

    int id = blockIdx.x;
    bool isdec = id >= 256;
    int lid2 = isdec ? id - 256 : id;
    int tile_m = lid2 >> 4, tile_n = lid2 & 15;
    int m0 = tile_m * 128, n0 = tile_n * 64;

    const __nv_bfloat16* Ahi = isdec ? g_dec_hi : g_enc_hi;
    const __nv_bfloat16* Alo = isdec ? g_dec_lo : g_enc_lo;
    const __nv_bfloat16* Bhi = g_w1t_hi + (isdec ? 1024 * 512 : 0);
    const __nv_bfloat16* Blo = g_w1t_lo + (isdec ? 1024 * 512 : 0);
    float* Cout = isdec ? g_dp : g_ep;

    float c[8][4];
    #pragma unroll
    for (int j = 0; j < 8; j++)
        #pragma unroll
        for (int q = 0; q < 4; q++) c[j][q] = 0.f;

    for (int kc = 0; kc < 16; kc++) {
        __syncthreads();
        // stage A (128x32 hi/lo): 2 uint4 per thread each
        #pragma unroll
        for (int it = 0; it < 2; it++) {
            int i = tid + it * 256;
            int r = i >> 2, g = i & 3;
            size_t sa = (size_t)(m0 + r) * 512 + kc * 32 + g * 8;
            *(uint4*)&sAH[r][g * 8] = *(const uint4*)(Ahi + sa);
            *(uint4*)&sAL[r][g * 8] = *(const uint4*)(Alo + sa);
        }
        // stage B (64x32 hi/lo): 1 uint4 per thread each
        {
            int r = tid >> 2, g = tid & 3;
            size_t sbx = (size_t)(n0 + r) * 512 + kc * 32 + g * 8;
            *(uint4*)&sBH[r][g * 8] = *(const uint4*)(Bhi + sbx);
            *(uint4*)&sBL[r][g * 8] = *(const uint4*)(Blo + sbx);
        }
        __syncthreads();

        #pragma unroll
        for (int ks = 0; ks < 2; ks++) {
            int kk = ks * 16;
            int rb = wid * 16;
            uint32_t aH[4], aL[4];
            aH[0] = *(const uint32_t*)&sAH[rb + gq][kk + tg * 2];
            aH[1] = *(const uint32_t*)&sAH[rb + gq + 8][kk + tg * 2];
            aH[2] = *(const uint32_t*)&sAH[rb + gq][kk + tg * 2 + 8];
            aH[3] = *(const uint32_t*)&sAH[rb + gq + 8][kk + tg * 2 + 8];
            aL[0] = *(const uint32_t*)&sAL[rb + gq][kk + tg * 2];
            aL[1] = *(const uint32_t*)&sAL[rb + gq + 8][kk + tg * 2];
            aL[2] = *(const uint32_t*)&sAL[rb + gq][kk + tg * 2 + 8];
            aL[3] = *(const uint32_t*)&sAL[rb + gq + 8][kk + tg * 2 + 8];
            #pragma unroll
            for (int nb = 0; nb < 8; nb++) {
                int n = nb * 8 + gq;
                uint32_t bH[2], bL[2];
                bH[0] = *(const uint32_t*)&sBH[n][kk + tg * 2];
                bH[1] = *(const uint32_t*)&sBH[n][kk + tg * 2 + 8];
                bL[0] = *(const uint32_t*)&sBL[n][kk + tg * 2];
                bL[1] = *(const uint32_t*)&sBL[n][kk + tg * 2 + 8];
                mma_bf16(c[nb], aH, bH);
                mma_bf16(c[nb], aH, bL);
                mma_bf16(c[nb], aL, bH);
            }
        }
    }

    // epilogue
    #pragma unroll
    for (int nb = 0; nb < 8; nb++) {
        int col = n0 + nb * 8 + tg * 2;
        float bb0 = 0.f, bb1 = 0.f;
        if (isdec) { bb0 = __ldg(b1 + col); bb1 = __ldg(b1 + col + 1); }
        int row = m0 + wid * 16 + gq;
        float2 v0 = make_float2(c[nb][0] + bb0, c[nb][1] + bb1);
        float2 v1 = make_float2(c[nb][2] + bb0, c[nb][3] + bb1);
        *(float2*)(Cout + (size_t)row * 1024 + col) = v0;
        *(float2*)(Cout + (size_t)(row + 8) * 1024 + col) = v1;
    }
}

// ---------------------------------------------------------------------------
// Fused kernel: per CTA: batch b, 2 t, 64 u -> M=128 rows (r = t_local*64+u),
// N=128 outputs, K=1024 in 16 chunks of 64. hidden generated on the fly.
// ep staged in smem once; tanh in f16x2; occ 2 for phase overlap.
// ---------------------------------------------------------------------------
__global__ __launch_bounds__(256, 2) void fused_kernel(float* __restrict__ out,
                                                       const float* __restrict__ b2) {
    __shared__ __align__(16) __half As[128][72];
    __shared__ __align__(16) __half Bs[128][72];
    __shared__ __align__(16) float  sep[2][1024];

    int tid = threadIdx.x, wid = tid >> 5, lane = tid & 31;
    int gq = lane >> 2, tg = lane & 3;
    int warp_m = wid >> 1, warp_n = wid & 1;

    int b  = blockIdx.x >> 7;
    int tp = blockIdx.x & 127;
    int t0 = tp * 2;

    // stage ep (2 x 1024 f32) once
    #pragma unroll
    for (int it = 0; it < 2; it++) {
        int i = tid + it * 256;             // float4 index, 512 total
        int r = i >> 8, k = (i & 255) * 4;
        *(float4*)&sep[r][k] = *(const float4*)(g_ep + (size_t)(b * 256 + t0 + r) * 1024 + k);
    }

    // A-gen mapping: thread -> (row, half of k-chunk)
    int arow = tid >> 1;
    int k0   = (tid & 1) * 32;
    int t_local = arow >> 6;
    const float* dp_base = g_dp + (size_t)(b * 64 + (arow & 63)) * 1024 + k0;

    float c[2][8][4];
    #pragma unroll
    for (int i = 0; i < 2; i++)
        #pragma unroll
        for (int j = 0; j < 8; j++)
            #pragma unroll
            for (int q = 0; q < 4; q++) c[i][j][q] = 0.f;

    for (int kc = 0; kc < 16; kc++) {
        __syncthreads();
        // stage W2^T tile (128 x 64 fp16)
        #pragma unroll
        for (int it = 0; it < 4; it++) {
            int i = tid + it * 256;
            int n = i >> 3, g = i & 7;
            *(uint4*)&Bs[n][g * 8] =
                *(const uint4*)(g_w2t + (size_t)n * 1024 + kc * 64 + g * 8);
        }
        // generate A = tanh(ep + dp) in f16x2 (each thread: 1 row, 32 k)
        {
            const float* eprow = &sep[t_local][kc * 64 + k0];
            const float* dprow = dp_base + kc * 64;
            #pragma unroll
            for (int q = 0; q < 4; q++) {
                float4 e0 = *(const float4*)(eprow + q * 8);
                float4 e1 = *(const float4*)(eprow + q * 8 + 4);
                float4 d0 = *(const float4*)(dprow + q * 8);
                float4 d1 = *(const float4*)(dprow + q * 8 + 4);
                __half2 s0 = __floats2half2_rn(e0.x + d0.x, e0.y + d0.y);
                __half2 s1 = __floats2half2_rn(e0.z + d0.z, e0.w + d0.w);
                __half2 s2 = __floats2half2_rn(e1.x + d1.x, e1.y + d1.y);
                __half2 s3 = __floats2half2_rn(e1.z + d1.z, e1.w + d1.w);
                uint4 v = make_uint4(tanh2_fast(*(uint32_t*)&s0),
                                     tanh2_fast(*(uint32_t*)&s1),
                                     tanh2_fast(*(uint32_t*)&s2),
                                     tanh2_fast(*(uint32_t*)&s3));
                *(uint4*)&As[arow][k0 + q * 8] = v;
            }
        }
        __syncthreads();

        // consume: 4 k-steps of 16
        #pragma unroll
        for (int ks = 0; ks < 4; ks++) {
            int kk = ks * 16;
            uint32_t aF[2][4];
            #pragma unroll
            for (int mt = 0; mt < 2; mt++) {
                int rb = warp_m * 32 + mt * 16;
                aF[mt][0] = *(const uint32_t*)&As[rb + gq][kk + tg * 2];
                aF[mt][1] = *(const uint32_t*)&As[rb + gq + 8][kk + tg * 2];
                aF[mt][2] = *(const uint32_t*)&As[rb + gq][kk + tg * 2 + 8];
                aF[mt][3] = *(const uint32_t*)&As[rb + gq + 8][kk + tg * 2 + 8];
            }
            #pragma unroll
            for (int nb = 0; nb < 8; nb++) {
                int n = warp_n * 64 + nb * 8 + gq;
                uint32_t bF[2];
                bF[0] = *(const uint32_t*)&Bs[n][kk + tg * 2];
                bF[1] = *(const uint32_t*)&Bs[n][kk + tg * 2 + 8];
                mma_f16(c[0][nb], aF[0], bF);
                mma_f16(c[1][nb], aF[1], bF);
            }
        }
    }

    // epilogue: out row index = b*16384 + t0*64 + r
    size_t orow0 = (size_t)b * 16384 + (size_t)t0 * 64;
    #pragma unroll
    for (int nb = 0; nb < 8; nb++) {
        int col = warp_n * 64 + nb * 8 + tg * 2;
        float bb0 = __ldg(b2 + col);
        float bb1 = __ldg(b2 + col + 1);
        #pragma unroll
        for (int mt = 0; mt < 2; mt++) {
            int row = warp_m * 32 + mt * 16 + gq;
            float2 v0 = make_float2(c[mt][nb][0] + bb0, c[mt][nb][1] + bb1);
            float2 v1 = make_float2(c[mt][nb][2] + bb0, c[mt][nb][3] + bb1);
            *(float2*)(out + (orow0 + row) * 128 + col) = v0;
            *(float2*)(out + (orow0 + row + 8) * 128 + col) = v1;
        }
    }
}

// ---------------------------------------------------------------------------
extern "C" void kernel_launch(void* const* d_in, const int* in_sizes, int n_in,
                              void* d_out, int out_size) {
    const float* enc = (const float*)d_in[0];
    const float* dec = (const float*)d_in[1];
    const float* W1  = (const float*)d_in[2];
    const float* b1  = (const float*)d_in[3];
    const float* W2  = (const float*)d_in[4];
    const float* b2  = (const float*)d_in[5];
    float* out = (float*)d_out;

    prep_split<<<4096, 256>>>(enc, dec);
    prep_w1t<<<1024, 256>>>(W1);
    prep_w2t<<<128, 256>>>(W2);
    proj_kernel<<<320, 256>>>(b1);
    fused_kernel<<<1024, 256>>>(out, b2);
}

// round 5
// speedup vs baseline: 2.0286x; 1.6442x over previous
#include <cuda_runtime.h>
#include <cuda_fp16.h>
#include <cuda_bf16.h>
#include <stdint.h>

// ---------------------------------------------------------------------------
// out[b,t,u,o] = sum_h tanh(ep[b,t,h] + dp[b,u,h]) * W2[h,o] + b2[o]
//   ep = enc @ W1[:512],  dp = dec @ W1[512:] + b1
// enc (8,256,512) dec (8,64,512) W1 (1024,1024) b1 (1024) W2 (1024,128) b2 (128)
// out (8,256,64,128) fp32.  Base ISA only (mma.sync + cp.async).
// ---------------------------------------------------------------------------

__device__ float          g_ep[2048 * 1024];          // enc proj fp32
__device__ float          g_dp[512 * 1024];           // dec proj + b1 fp32
__device__ __nv_bfloat16  g_enc_hi[2048 * 512];
__device__ __nv_bfloat16  g_enc_lo[2048 * 512];
__device__ __nv_bfloat16  g_dec_hi[512 * 512];
__device__ __nv_bfloat16  g_dec_lo[512 * 512];
__device__ __nv_bfloat16  g_w1t_hi[2 * 1024 * 512];   // [part][n][k]
__device__ __nv_bfloat16  g_w1t_lo[2 * 1024 * 512];
__device__ __half         g_w2t[128 * 1024];          // [n][k] = W2[k][n]

__device__ __forceinline__ uint32_t tanh2_fast(uint32_t x2) {   // half2 tanh
    uint32_t r; asm("tanh.approx.f16x2 %0, %1;" : "=r"(r) : "r"(x2)); return r;
}

__device__ __forceinline__ void mma_f16(float* c, const uint32_t* a, const uint32_t* b) {
    asm volatile("mma.sync.aligned.m16n8k16.row.col.f32.f16.f16.f32 "
        "{%0,%1,%2,%3}, {%4,%5,%6,%7}, {%8,%9}, {%0,%1,%2,%3};"
        : "+f"(c[0]), "+f"(c[1]), "+f"(c[2]), "+f"(c[3])
        : "r"(a[0]), "r"(a[1]), "r"(a[2]), "r"(a[3]), "r"(b[0]), "r"(b[1]));
}
__device__ __forceinline__ void mma_bf16(float* c, const uint32_t* a, const uint32_t* b) {
    asm volatile("mma.sync.aligned.m16n8k16.row.col.f32.bf16.bf16.f32 "
        "{%0,%1,%2,%3}, {%4,%5,%6,%7}, {%8,%9}, {%0,%1,%2,%3};"
        : "+f"(c[0]), "+f"(c[1]), "+f"(c[2]), "+f"(c[3])
        : "r"(a[0]), "r"(a[1]), "r"(a[2]), "r"(a[3]), "r"(b[0]), "r"(b[1]));
}

__device__ __forceinline__ void cp16(void* sdst, const void* gsrc) {
    uint32_t s = (uint32_t)__cvta_generic_to_shared(sdst);
    asm volatile("cp.async.cg.shared.global [%0], [%1], 16;" :: "r"(s), "l"(gsrc) : "memory");
}
#define CP_COMMIT() asm volatile("cp.async.commit_group;" ::: "memory")
#define CP_WAIT0()  asm volatile("cp.async.wait_group 0;" ::: "memory")

// ---------------------------------------------------------------------------
// Prep kernels
// ---------------------------------------------------------------------------
__global__ __launch_bounds__(256) void prep_split(const float* __restrict__ enc,
                                                  const float* __restrict__ dec) {
    int i = blockIdx.x * 256 + threadIdx.x;
    if (i < 2048 * 512) {
        float x = enc[i];
        __nv_bfloat16 h = __float2bfloat16(x);
        g_enc_hi[i] = h;
        g_enc_lo[i] = __float2bfloat16(x - __bfloat162float(h));
    }
    if (i < 512 * 512) {
        float x = dec[i];
        __nv_bfloat16 h = __float2bfloat16(x);
        g_dec_hi[i] = h;
        g_dec_lo[i] = __float2bfloat16(x - __bfloat162float(h));
    }
}

__global__ __launch_bounds__(256) void prep_w1t(const float* __restrict__ W1) {
    __shared__ float tile[32][33];
    int tx = threadIdx.x & 31, ty = threadIdx.x >> 5;
    int bx = blockIdx.x & 31;        // n tile
    int by = blockIdx.x >> 5;        // k tile
    #pragma unroll
    for (int r = 0; r < 4; r++)
        tile[ty + r * 8][tx] = W1[(by * 32 + ty + r * 8) * 1024 + bx * 32 + tx];
    __syncthreads();
    #pragma unroll
    for (int r = 0; r < 4; r++) {
        int n  = bx * 32 + ty + r * 8;
        int kk = by * 32 + tx;
        float x = tile[tx][ty + r * 8];
        int p = kk >> 9;
        int idx = (p * 1024 + n) * 512 + (kk & 511);
        __nv_bfloat16 h = __float2bfloat16(x);
        g_w1t_hi[idx] = h;
        g_w1t_lo[idx] = __float2bfloat16(x - __bfloat162float(h));
    }
}

__global__ __launch_bounds__(256) void prep_w2t(const float* __restrict__ W2) {
    __shared__ float tile[32][33];
    int tx = threadIdx.x & 31, ty = threadIdx.x >> 5;
    int bx = blockIdx.x & 3;          // n tile
    int by = blockIdx.x >> 2;         // k tile
    #pragma unroll
    for (int r = 0; r < 4; r++)
        tile[ty + r * 8][tx] = W2[(by * 32 + ty + r * 8) * 128 + bx * 32 + tx];
    __syncthreads();
    #pragma unroll
    for (int r = 0; r < 4; r++) {
        int n = bx * 32 + ty + r * 8;
        int k = by * 32 + tx;
        g_w2t[n * 1024 + k] = __float2half(tile[tx][ty + r * 8]);
    }
}

// ---------------------------------------------------------------------------
// Projection: C tile [128 x 64] = A[128x512] @ Wt[64x512]^T  (bf16 hi/lo x3)
// 320 CTAs: 0..255 enc, 256..319 dec (+b1). cp.async double-buffered.
// smem per buffer: AH 10240 | AL 10240 | BH 5120 | BL 5120 = 30720; x2 = 61440
// rows padded to 40 bf16 (80B) -> conflict-free frag LDS.
// ---------------------------------------------------------------------------
#define PROJ_BUF 30720
#define PROJ_SMEM (2 * PROJ_BUF)

__global__ __launch_bounds__(256, 2) void proj_kernel(const float* __restrict__ b1) {
    extern __shared__ char smem[];

    int tid = threadIdx.x, wid = tid >> 5, lane = tid & 31;
    int gq = lane >> 2, tg = lane & 3;

    int id = blockIdx.x;
    bool isdec = id >= 256;
    int lid2 = isdec ? id - 256 : id;
    int tile_m = lid2 >> 4, tile_n = lid2 & 15;
    int m0 = tile_m * 128, n0 = tile_n * 64;

    const char* Ahi = (const char*)(isdec ? g_dec_hi : g_enc_hi);
    const char* Alo = (const char*)(isdec ? g_dec_lo : g_enc_lo);
    const char* Bhi = (const char*)(g_w1t_hi + (isdec ? 1024 * 512 : 0));
    const char* Blo = (const char*)(g_w1t_lo + (isdec ? 1024 * 512 : 0));
    float* Cout = isdec ? g_dp : g_ep;

    // issue staging for chunk kc into buffer kc&1
    auto issue = [&](int kc) {
        char* base = smem + (kc & 1) * PROJ_BUF;
        #pragma unroll
        for (int it = 0; it < 2; it++) {
            int i = tid + it * 256;          // 512: r = i>>2, sg = i&3
            int r = i >> 2, sg = i & 3;
            size_t gsrc = (size_t)(m0 + r) * 1024 + kc * 64 + sg * 16;
            cp16(base + r * 80 + sg * 16, Ahi + gsrc);
            cp16(base + 10240 + r * 80 + sg * 16, Alo + gsrc);
        }
        {
            int r = tid >> 2, sg = tid & 3;  // 256: 64 rows x 4 segs
            size_t gsrc = (size_t)(n0 + r) * 1024 + kc * 64 + sg * 16;
            cp16(base + 20480 + r * 80 + sg * 16, Bhi + gsrc);
            cp16(base + 25600 + r * 80 + sg * 16, Blo + gsrc);
        }
    };

    float c[8][4];
    #pragma unroll
    for (int j = 0; j < 8; j++)
        #pragma unroll
        for (int q = 0; q < 4; q++) c[j][q] = 0.f;

    issue(0);
    CP_COMMIT();

    for (int kc = 0; kc < 16; kc++) {
        CP_WAIT0();
        __syncthreads();
        if (kc + 1 < 16) { issue(kc + 1); CP_COMMIT(); }

        const char* base = smem + (kc & 1) * PROJ_BUF;
        const __nv_bfloat16* AH = (const __nv_bfloat16*)base;
        const __nv_bfloat16* AL = (const __nv_bfloat16*)(base + 10240);
        const __nv_bfloat16* BH = (const __nv_bfloat16*)(base + 20480);
        const __nv_bfloat16* BL = (const __nv_bfloat16*)(base + 25600);

        #pragma unroll
        for (int ks = 0; ks < 2; ks++) {
            int kk = ks * 16;
            int rb = wid * 16;
            uint32_t aH[4], aL[4];
            aH[0] = *(const uint32_t*)&AH[(rb + gq) * 40 + kk + tg * 2];
            aH[1] = *(const uint32_t*)&AH[(rb + gq + 8) * 40 + kk + tg * 2];
            aH[2] = *(const uint32_t*)&AH[(rb + gq) * 40 + kk + tg * 2 + 8];
            aH[3] = *(const uint32_t*)&AH[(rb + gq + 8) * 40 + kk + tg * 2 + 8];
            aL[0] = *(const uint32_t*)&AL[(rb + gq) * 40 + kk + tg * 2];
            aL[1] = *(const uint32_t*)&AL[(rb + gq + 8) * 40 + kk + tg * 2];
            aL[2] = *(const uint32_t*)&AL[(rb + gq) * 40 + kk + tg * 2 + 8];
            aL[3] = *(const uint32_t*)&AL[(rb + gq + 8) * 40 + kk + tg * 2 + 8];
            #pragma unroll
            for (int nb = 0; nb < 8; nb++) {
                int n = nb * 8 + gq;
                uint32_t bH[2], bL[2];
                bH[0] = *(const uint32_t*)&BH[n * 40 + kk + tg * 2];
                bH[1] = *(const uint32_t*)&BH[n * 40 + kk + tg * 2 + 8];
                bL[0] = *(const uint32_t*)&BL[n * 40 + kk + tg * 2];
                bL[1] = *(const uint32_t*)&BL[n * 40 + kk + tg * 2 + 8];
                mma_bf16(c[nb], aH, bH);
                mma_bf16(c[nb], aH, bL);
                mma_bf16(c[nb], aL, bH);
            }
        }
    }

    // epilogue
    #pragma unroll
    for (int nb = 0; nb < 8; nb++) {
        int col = n0 + nb * 8 + tg * 2;
        float bb0 = 0.f, bb1 = 0.f;
        if (isdec) { bb0 = __ldg(b1 + col); bb1 = __ldg(b1 + col + 1); }
        int row = m0 + wid * 16 + gq;
        float2 v0 = make_float2(c[nb][0] + bb0, c[nb][1] + bb1);
        float2 v1 = make_float2(c[nb][2] + bb0, c[nb][3] + bb1);
        *(float2*)(Cout + (size_t)row * 1024 + col) = v0;
        *(float2*)(Cout + (size_t)(row + 8) * 1024 + col) = v1;
    }
}

// ---------------------------------------------------------------------------
// Fused kernel: CTA = (batch b, 2 t, 64 u) -> M=128 rows x N=128, K=1024/64.
// Warp w: rows w*16..w*16+15, all 128 n.  A = tanh(ep+dp) generated directly
// into mma fragments (no smem round-trip).  Bs + dp double-buffered cp.async.
// smem: Bs 2x[128][72]h (36864) | dps 2x[64][72]f (36864) | sep [2][1024]f (8192)
// ---------------------------------------------------------------------------
#define FB_BS    0
#define FB_DPS   36864
#define FB_SEP   73728
#define FUSED_SMEM (73728 + 8192)

__global__ __launch_bounds__(256, 2) void fused_kernel(float* __restrict__ out,
                                                       const float* __restrict__ b2) {
    extern __shared__ char smem[];
    __half* Bs  = (__half*)(smem + FB_BS);     // [2][128][72]
    float*  dps = (float*)(smem + FB_DPS);     // [2][64][72]
    float*  sep = (float*)(smem + FB_SEP);     // [2][1024]

    int tid = threadIdx.x, wid = tid >> 5, lane = tid & 31;
    int gq = lane >> 2, tg = lane & 3;

    int b  = blockIdx.x >> 7;
    int tp = blockIdx.x & 127;
    int t0 = tp * 2;

    // stage ep (2 x 1024 f32) once
    #pragma unroll
    for (int it = 0; it < 2; it++) {
        int i = tid + it * 256;             // float4 index, 512 total
        int r = i >> 8, k = (i & 255) * 4;
        *(float4*)&sep[r * 1024 + k] =
            *(const float4*)(g_ep + (size_t)(b * 256 + t0 + r) * 1024 + k);
    }

    auto issue = [&](int kc) {
        int buf = kc & 1;
        #pragma unroll
        for (int it = 0; it < 4; it++) {     // Bs: 1024 segs
            int i = tid + it * 256;
            int r = i >> 3, sg = i & 7;
            cp16((char*)Bs + buf * 18432 + r * 144 + sg * 16,
                 (const char*)g_w2t + (size_t)r * 2048 + kc * 128 + sg * 16);
        }
        #pragma unroll
        for (int it = 0; it < 4; it++) {     // dps: 1024 segs
            int i = tid + it * 256;
            int u = i >> 4, sg = i & 15;
            cp16((char*)dps + buf * 18432 + u * 288 + sg * 16,
                 (const char*)g_dp + (size_t)(b * 64 + u) * 4096 + kc * 256 + sg * 16);
        }
    };

    int u0 = (wid & 3) * 16 + gq;     // dp row of frag-row gq  (row+8 -> u0+8)
    int tl = wid >> 2;                // t_local of this warp's rows

    float c[16][4];
    #pragma unroll
    for (int j = 0; j < 16; j++)
        #pragma unroll
        for (int q = 0; q < 4; q++) c[j][q] = 0.f;

    issue(0);
    CP_COMMIT();

    for (int kc = 0; kc < 16; kc++) {
        CP_WAIT0();
        __syncthreads();
        if (kc + 1 < 16) { issue(kc + 1); CP_COMMIT(); }

        int buf = kc & 1;
        const float*  ept = sep + tl * 1024 + kc * 64;
        const float*  dpb = dps + buf * 4608;
        const __half* bsb = Bs + buf * 9216;

        // A fragments in registers: tanh(ep + dp) -> half2
        uint32_t areg[4][4];
        #pragma unroll
        for (int ks = 0; ks < 4; ks++) {
            #pragma unroll
            for (int kp = 0; kp < 2; kp++) {
                int k = ks * 16 + tg * 2 + kp * 8;
                float2 e  = *(const float2*)(ept + k);
                float2 da = *(const float2*)(dpb + u0 * 72 + k);
                float2 db = *(const float2*)(dpb + (u0 + 8) * 72 + k);
                __half2 ha = __floats2half2_rn(e.x + da.x, e.y + da.y);
                __half2 hb = __floats2half2_rn(e.x + db.x, e.y + db.y);
                areg[ks][kp * 2 + 0] = tanh2_fast(*(uint32_t*)&ha);
                areg[ks][kp * 2 + 1] = tanh2_fast(*(uint32_t*)&hb);
            }
        }

        // consume: 4 k-steps x 16 n-blocks
        #pragma unroll
        for (int ks = 0; ks < 4; ks++) {
            #pragma unroll
            for (int nb = 0; nb < 16; nb++) {
                const __half* bp = bsb + (nb * 8 + gq) * 72 + ks * 16 + tg * 2;
                uint32_t bf[2];
                bf[0] = *(const uint32_t*)bp;
                bf[1] = *(const uint32_t*)(bp + 8);
                mma_f16(c[nb], areg[ks], bf);
            }
        }
    }

    // epilogue: rows contiguous: global row = b*16384 + t0*64 + local
    size_t orow0 = (size_t)b * 16384 + (size_t)t0 * 64;
    int row0 = wid * 16 + gq;
    #pragma unroll
    for (int nb = 0; nb < 16; nb++) {
        int col = nb * 8 + tg * 2;
        float bb0 = __ldg(b2 + col);
        float bb1 = __ldg(b2 + col + 1);
        float2 v0 = make_float2(c[nb][0] + bb0, c[nb][1] + bb1);
        float2 v1 = make_float2(c[nb][2] + bb0, c[nb][3] + bb1);
        *(float2*)(out + (orow0 + row0) * 128 + col) = v0;
        *(float2*)(out + (orow0 + row0 + 8) * 128 + col) = v1;
    }
}

// ---------------------------------------------------------------------------
extern "C" void kernel_launch(void* const* d_in, const int* in_sizes, int n_in,
                              void* d_out, int out_size) {
    const float* enc = (const float*)d_in[0];
    const float* dec = (const float*)d_in[1];
    const float* W1  = (const float*)d_in[2];
    const float* b1  = (const float*)d_in[3];
    const float* W2  = (const float*)d_in[4];
    const float* b2  = (const float*)d_in[5];
    float* out = (float*)d_out;

    cudaFuncSetAttribute(proj_kernel,  cudaFuncAttributeMaxDynamicSharedMemorySize, PROJ_SMEM);
    cudaFuncSetAttribute(fused_kernel, cudaFuncAttributeMaxDynamicSharedMemorySize, FUSED_SMEM);

    prep_split<<<4096, 256>>>(enc, dec);
    prep_w1t<<<1024, 256>>>(W1);
    prep_w2t<<<128, 256>>>(W2);
    proj_kernel<<<320, 256, PROJ_SMEM>>>(b1);
    fused_kernel<<<1024, 256, FUSED_SMEM>>>(out, b2);
}

// round 6
// speedup vs baseline: 2.0560x; 1.0135x over previous
#include <cuda_runtime.h>
#include <cuda_fp16.h>
#include <cuda_bf16.h>
#include <stdint.h>

// ---------------------------------------------------------------------------
// out[b,t,u,o] = sum_h tanh(ep[b,t,h] + dp[b,u,h]) * W2[h,o] + b2[o]
//   ep = enc @ W1[:512],  dp = dec @ W1[512:] + b1
// enc (8,256,512) dec (8,64,512) W1 (1024,1024) b1 (1024) W2 (1024,128) b2 (128)
// out (8,256,64,128) fp32.  Base ISA only (mma.sync + cp.async).
// ---------------------------------------------------------------------------

__device__ float          g_ep[2048 * 1024];          // enc proj fp32
__device__ float          g_dp[512 * 1024];           // dec proj + b1 fp32
__device__ __nv_bfloat16  g_enc_hi[2048 * 512];
__device__ __nv_bfloat16  g_enc_lo[2048 * 512];
__device__ __nv_bfloat16  g_dec_hi[512 * 512];
__device__ __nv_bfloat16  g_dec_lo[512 * 512];
__device__ __nv_bfloat16  g_w1t_hi[2 * 1024 * 512];   // [part][n][k]
__device__ __nv_bfloat16  g_w1t_lo[2 * 1024 * 512];
__device__ __half         g_w2t[128 * 1024];          // [n][k] = W2[k][n]

__device__ __forceinline__ uint32_t tanh2_fast(uint32_t x2) {   // half2 tanh
    uint32_t r; asm("tanh.approx.f16x2 %0, %1;" : "=r"(r) : "r"(x2)); return r;
}

__device__ __forceinline__ void mma_f16(float* c, const uint32_t* a, const uint32_t* b) {
    asm volatile("mma.sync.aligned.m16n8k16.row.col.f32.f16.f16.f32 "
        "{%0,%1,%2,%3}, {%4,%5,%6,%7}, {%8,%9}, {%0,%1,%2,%3};"
        : "+f"(c[0]), "+f"(c[1]), "+f"(c[2]), "+f"(c[3])
        : "r"(a[0]), "r"(a[1]), "r"(a[2]), "r"(a[3]), "r"(b[0]), "r"(b[1]));
}
__device__ __forceinline__ void mma_bf16(float* c, const uint32_t* a, const uint32_t* b) {
    asm volatile("mma.sync.aligned.m16n8k16.row.col.f32.bf16.bf16.f32 "
        "{%0,%1,%2,%3}, {%4,%5,%6,%7}, {%8,%9}, {%0,%1,%2,%3};"
        : "+f"(c[0]), "+f"(c[1]), "+f"(c[2]), "+f"(c[3])
        : "r"(a[0]), "r"(a[1]), "r"(a[2]), "r"(a[3]), "r"(b[0]), "r"(b[1]));
}

__device__ __forceinline__ void cp16(void* sdst, const void* gsrc) {
    uint32_t s = (uint32_t)__cvta_generic_to_shared(sdst);
    asm volatile("cp.async.cg.shared.global [%0], [%1], 16;" :: "r"(s), "l"(gsrc) : "memory");
}
#define CP_COMMIT() asm volatile("cp.async.commit_group;" ::: "memory")
#define CP_WAIT0()  asm volatile("cp.async.wait_group 0;" ::: "memory")

// ---------------------------------------------------------------------------
// Prep kernels
// ---------------------------------------------------------------------------
__global__ __launch_bounds__(256) void prep_split(const float* __restrict__ enc,
                                                  const float* __restrict__ dec) {
    int i = blockIdx.x * 256 + threadIdx.x;
    if (i < 2048 * 512) {
        float x = enc[i];
        __nv_bfloat16 h = __float2bfloat16(x);
        g_enc_hi[i] = h;
        g_enc_lo[i] = __float2bfloat16(x - __bfloat162float(h));
    }
    if (i < 512 * 512) {
        float x = dec[i];
        __nv_bfloat16 h = __float2bfloat16(x);
        g_dec_hi[i] = h;
        g_dec_lo[i] = __float2bfloat16(x - __bfloat162float(h));
    }
}

__global__ __launch_bounds__(256) void prep_w1t(const float* __restrict__ W1) {
    __shared__ float tile[32][33];
    int tx = threadIdx.x & 31, ty = threadIdx.x >> 5;
    int bx = blockIdx.x & 31;        // n tile
    int by = blockIdx.x >> 5;        // k tile
    #pragma unroll
    for (int r = 0; r < 4; r++)
        tile[ty + r * 8][tx] = W1[(by * 32 + ty + r * 8) * 1024 + bx * 32 + tx];
    __syncthreads();
    #pragma unroll
    for (int r = 0; r < 4; r++) {
        int n  = bx * 32 + ty + r * 8;
        int kk = by * 32 + tx;
        float x = tile[tx][ty + r * 8];
        int p = kk >> 9;
        int idx = (p * 1024 + n) * 512 + (kk & 511);
        __nv_bfloat16 h = __float2bfloat16(x);
        g_w1t_hi[idx] = h;
        g_w1t_lo[idx] = __float2bfloat16(x - __bfloat162float(h));
    }
}

__global__ __launch_bounds__(256) void prep_w2t(const float* __restrict__ W2) {
    __shared__ float tile[32][33];
    int tx = threadIdx.x & 31, ty = threadIdx.x >> 5;
    int bx = blockIdx.x & 3;          // n tile
    int by = blockIdx.x >> 2;         // k tile
    #pragma unroll
    for (int r = 0; r < 4; r++)
        tile[ty + r * 8][tx] = W2[(by * 32 + ty + r * 8) * 128 + bx * 32 + tx];
    __syncthreads();
    #pragma unroll
    for (int r = 0; r < 4; r++) {
        int n = bx * 32 + ty + r * 8;
        int k = by * 32 + tx;
        g_w2t[n * 1024 + k] = __float2half(tile[tx][ty + r * 8]);
    }
}

// ---------------------------------------------------------------------------
// Projection: C tile [128 x 64] = A[128x512] @ Wt[64x512]^T  (bf16 hi/lo x3)
// 320 CTAs: 0..255 enc, 256..319 dec (+b1). cp.async double-buffered, occ 3.
// ---------------------------------------------------------------------------
#define PROJ_BUF 30720
#define PROJ_SMEM (2 * PROJ_BUF)

__global__ __launch_bounds__(256, 3) void proj_kernel(const float* __restrict__ b1) {
    extern __shared__ char smem[];

    int tid = threadIdx.x, wid = tid >> 5, lane = tid & 31;
    int gq = lane >> 2, tg = lane & 3;

    int id = blockIdx.x;
    bool isdec = id >= 256;
    int lid2 = isdec ? id - 256 : id;
    int tile_m = lid2 >> 4, tile_n = lid2 & 15;
    int m0 = tile_m * 128, n0 = tile_n * 64;

    const char* Ahi = (const char*)(isdec ? g_dec_hi : g_enc_hi);
    const char* Alo = (const char*)(isdec ? g_dec_lo : g_enc_lo);
    const char* Bhi = (const char*)(g_w1t_hi + (isdec ? 1024 * 512 : 0));
    const char* Blo = (const char*)(g_w1t_lo + (isdec ? 1024 * 512 : 0));
    float* Cout = isdec ? g_dp : g_ep;

    auto issue = [&](int kc) {
        char* base = smem + (kc & 1) * PROJ_BUF;
        #pragma unroll
        for (int it = 0; it < 2; it++) {
            int i = tid + it * 256;
            int r = i >> 2, sg = i & 3;
            size_t gsrc = (size_t)(m0 + r) * 1024 + kc * 64 + sg * 16;
            cp16(base + r * 80 + sg * 16, Ahi + gsrc);
            cp16(base + 10240 + r * 80 + sg * 16, Alo + gsrc);
        }
        {
            int r = tid >> 2, sg = tid & 3;
            size_t gsrc = (size_t)(n0 + r) * 1024 + kc * 64 + sg * 16;
            cp16(base + 20480 + r * 80 + sg * 16, Bhi + gsrc);
            cp16(base + 25600 + r * 80 + sg * 16, Blo + gsrc);
        }
    };

    float c[8][4];
    #pragma unroll
    for (int j = 0; j < 8; j++)
        #pragma unroll
        for (int q = 0; q < 4; q++) c[j][q] = 0.f;

    issue(0);
    CP_COMMIT();

    for (int kc = 0; kc < 16; kc++) {
        CP_WAIT0();
        __syncthreads();
        if (kc + 1 < 16) { issue(kc + 1); CP_COMMIT(); }

        const char* base = smem + (kc & 1) * PROJ_BUF;
        const __nv_bfloat16* AH = (const __nv_bfloat16*)base;
        const __nv_bfloat16* AL = (const __nv_bfloat16*)(base + 10240);
        const __nv_bfloat16* BH = (const __nv_bfloat16*)(base + 20480);
        const __nv_bfloat16* BL = (const __nv_bfloat16*)(base + 25600);

        #pragma unroll
        for (int ks = 0; ks < 2; ks++) {
            int kk = ks * 16;
            int rb = wid * 16;
            uint32_t aH[4], aL[4];
            aH[0] = *(const uint32_t*)&AH[(rb + gq) * 40 + kk + tg * 2];
            aH[1] = *(const uint32_t*)&AH[(rb + gq + 8) * 40 + kk + tg * 2];
            aH[2] = *(const uint32_t*)&AH[(rb + gq) * 40 + kk + tg * 2 + 8];
            aH[3] = *(const uint32_t*)&AH[(rb + gq + 8) * 40 + kk + tg * 2 + 8];
            aL[0] = *(const uint32_t*)&AL[(rb + gq) * 40 + kk + tg * 2];
            aL[1] = *(const uint32_t*)&AL[(rb + gq + 8) * 40 + kk + tg * 2];
            aL[2] = *(const uint32_t*)&AL[(rb + gq) * 40 + kk + tg * 2 + 8];
            aL[3] = *(const uint32_t*)&AL[(rb + gq + 8) * 40 + kk + tg * 2 + 8];
            #pragma unroll
            for (int nb = 0; nb < 8; nb++) {
                int n = nb * 8 + gq;
                uint32_t bH[2], bL[2];
                bH[0] = *(const uint32_t*)&BH[n * 40 + kk + tg * 2];
                bH[1] = *(const uint32_t*)&BH[n * 40 + kk + tg * 2 + 8];
                bL[0] = *(const uint32_t*)&BL[n * 40 + kk + tg * 2];
                bL[1] = *(const uint32_t*)&BL[n * 40 + kk + tg * 2 + 8];
                mma_bf16(c[nb], aH, bH);
                mma_bf16(c[nb], aH, bL);
                mma_bf16(c[nb], aL, bH);
            }
        }
    }

    #pragma unroll
    for (int nb = 0; nb < 8; nb++) {
        int col = n0 + nb * 8 + tg * 2;
        float bb0 = 0.f, bb1 = 0.f;
        if (isdec) { bb0 = __ldg(b1 + col); bb1 = __ldg(b1 + col + 1); }
        int row = m0 + wid * 16 + gq;
        float2 v0 = make_float2(c[nb][0] + bb0, c[nb][1] + bb1);
        float2 v1 = make_float2(c[nb][2] + bb0, c[nb][3] + bb1);
        *(float2*)(Cout + (size_t)row * 1024 + col) = v0;
        *(float2*)(Cout + (size_t)(row + 8) * 1024 + col) = v1;
    }
}

// ---------------------------------------------------------------------------
// Fused kernel: CTA = (batch b, 4 t, 64 u) -> M=256 rows x N=128, K=1024/64.
// Warp w (8 warps): rows w*32..w*32+31 (mt=2), all 128 n. A = tanh(ep+dp)
// generated into fragments. Bs + dp double-buffered cp.async. occ 1, 512 CTAs.
// smem: Bs 2x[128][72]h (36864) | dps 2x[64][72]f (36864) | sep [4][1024]f (16384)
// ---------------------------------------------------------------------------
#define FB_BS    0
#define FB_DPS   36864
#define FB_SEP   73728
#define FUSED_SMEM (73728 + 16384)

__global__ __launch_bounds__(256, 1) void fused_kernel(float* __restrict__ out,
                                                       const float* __restrict__ b2) {
    extern __shared__ char smem[];
    __half* Bs  = (__half*)(smem + FB_BS);     // [2][128][72]
    float*  dps = (float*)(smem + FB_DPS);     // [2][64][72]
    float*  sep = (float*)(smem + FB_SEP);     // [4][1024]

    int tid = threadIdx.x, wid = tid >> 5, lane = tid & 31;
    int gq = lane >> 2, tg = lane & 3;

    int b  = blockIdx.x >> 6;
    int tp = blockIdx.x & 63;
    int t0 = tp * 4;

    // stage ep (4 x 1024 f32) once
    #pragma unroll
    for (int it = 0; it < 4; it++) {
        int i = tid + it * 256;             // float4 index, 1024 total
        int r = i >> 8, k = (i & 255) * 4;
        *(float4*)&sep[r * 1024 + k] =
            *(const float4*)(g_ep + (size_t)(b * 256 + t0 + r) * 1024 + k);
    }

    auto issue = [&](int kc) {
        int buf = kc & 1;
        #pragma unroll
        for (int it = 0; it < 4; it++) {     // Bs: 1024 segs of 16B
            int i = tid + it * 256;
            int r = i >> 3, sg = i & 7;
            cp16((char*)Bs + buf * 18432 + r * 144 + sg * 16,
                 (const char*)g_w2t + (size_t)r * 2048 + kc * 128 + sg * 16);
        }
        #pragma unroll
        for (int it = 0; it < 4; it++) {     // dps: 1024 segs of 16B
            int i = tid + it * 256;
            int u = i >> 4, sg = i & 15;
            cp16((char*)dps + buf * 18432 + u * 288 + sg * 16,
                 (const char*)g_dp + (size_t)(b * 64 + u) * 4096 + kc * 256 + sg * 16);
        }
    };

    int tl = wid >> 1;                 // t_local of this warp's 32 rows
    int u0 = (wid & 1) * 32 + gq;      // u of frag-row gq in mt=0 tile

    float c[2][16][4];
    #pragma unroll
    for (int i = 0; i < 2; i++)
        #pragma unroll
        for (int j = 0; j < 16; j++)
            #pragma unroll
            for (int q = 0; q < 4; q++) c[i][j][q] = 0.f;

    issue(0);
    CP_COMMIT();

    for (int kc = 0; kc < 16; kc++) {
        CP_WAIT0();
        __syncthreads();
        if (kc + 1 < 16) { issue(kc + 1); CP_COMMIT(); }

        int buf = kc & 1;
        const float*  ept = sep + tl * 1024 + kc * 64;
        const float*  dpb = dps + buf * 4608;
        const __half* bsb = Bs + buf * 9216;

        #pragma unroll
        for (int ks = 0; ks < 4; ks++) {
            // A fragments for both 16-row tiles of this warp
            uint32_t areg[2][4];
            #pragma unroll
            for (int kp = 0; kp < 2; kp++) {
                int k = ks * 16 + tg * 2 + kp * 8;
                float2 e = *(const float2*)(ept + k);
                #pragma unroll
                for (int mt = 0; mt < 2; mt++) {
                    int u = u0 + mt * 16;
                    float2 da = *(const float2*)(dpb + u * 72 + k);
                    float2 db = *(const float2*)(dpb + (u + 8) * 72 + k);
                    __half2 ha = __floats2half2_rn(e.x + da.x, e.y + da.y);
                    __half2 hb = __floats2half2_rn(e.x + db.x, e.y + db.y);
                    areg[mt][kp * 2 + 0] = tanh2_fast(*(uint32_t*)&ha);
                    areg[mt][kp * 2 + 1] = tanh2_fast(*(uint32_t*)&hb);
                }
            }
            // consume: 16 n-blocks, B frag reused for both mt tiles
            #pragma unroll
            for (int nb = 0; nb < 16; nb++) {
                const __half* bp = bsb + (nb * 8 + gq) * 72 + ks * 16 + tg * 2;
                uint32_t bf[2];
                bf[0] = *(const uint32_t*)bp;
                bf[1] = *(const uint32_t*)(bp + 8);
                mma_f16(c[0][nb], areg[0], bf);
                mma_f16(c[1][nb], areg[1], bf);
            }
        }
    }

    // epilogue: global row = b*16384 + t0*64 + local (contiguous)
    size_t orow0 = (size_t)b * 16384 + (size_t)t0 * 64;
    #pragma unroll
    for (int mt = 0; mt < 2; mt++) {
        int row0 = wid * 32 + mt * 16 + gq;
        #pragma unroll
        for (int nb = 0; nb < 16; nb++) {
            int col = nb * 8 + tg * 2;
            float bb0 = __ldg(b2 + col);
            float bb1 = __ldg(b2 + col + 1);
            float2 v0 = make_float2(c[mt][nb][0] + bb0, c[mt][nb][1] + bb1);
            float2 v1 = make_float2(c[mt][nb][2] + bb0, c[mt][nb][3] + bb1);
            *(float2*)(out + (orow0 + row0) * 128 + col) = v0;
            *(float2*)(out + (orow0 + row0 + 8) * 128 + col) = v1;
        }
    }
}

// ---------------------------------------------------------------------------
extern "C" void kernel_launch(void* const* d_in, const int* in_sizes, int n_in,
                              void* d_out, int out_size) {
    const float* enc = (const float*)d_in[0];
    const float* dec = (const float*)d_in[1];
    const float* W1  = (const float*)d_in[2];
    const float* b1  = (const float*)d_in[3];
    const float* W2  = (const float*)d_in[4];
    const float* b2  = (const float*)d_in[5];
    float* out = (float*)d_out;

    cudaFuncSetAttribute(proj_kernel,  cudaFuncAttributeMaxDynamicSharedMemorySize, PROJ_SMEM);
    cudaFuncSetAttribute(fused_kernel, cudaFuncAttributeMaxDynamicSharedMemorySize, FUSED_SMEM);

    prep_split<<<4096, 256>>>(enc, dec);
    prep_w1t<<<1024, 256>>>(W1);
    prep_w2t<<<128, 256>>>(W2);
    proj_kernel<<<320, 256, PROJ_SMEM>>>(b1);
    fused_kernel<<<512, 256, FUSED_SMEM>>>(out, b2);
}

// round 7
// speedup vs baseline: 2.1227x; 1.0324x over previous
#include <cuda_runtime.h>
#include <cuda_fp16.h>
#include <stdint.h>

// ---------------------------------------------------------------------------
// out[b,t,u,o] = sum_h tanh(ep[b,t,h] + dp[b,u,h]) * W2[h,o] + b2[o]
//   ep = enc @ W1[:512],  dp = dec @ W1[512:] + b1
// enc (8,256,512) dec (8,64,512) W1 (1024,1024) b1 (1024) W2 (1024,128) b2 (128)
// out (8,256,64,128) fp32.  Base ISA only (mma.sync + cp.async + ldmatrix).
// ---------------------------------------------------------------------------

__device__ float   g_ep[2048 * 1024];          // enc proj fp32
__device__ float   g_dp[512 * 1024];           // dec proj + b1 fp32
__device__ __half  g_enc_hi[2048 * 512];
__device__ __half  g_enc_lo[2048 * 512];
__device__ __half  g_dec_hi[512 * 512];
__device__ __half  g_dec_lo[512 * 512];
__device__ __half  g_w1t_hi[2 * 1024 * 512];   // [part][n][k]
__device__ __half  g_w1t_lo[2 * 1024 * 512];
__device__ __half  g_w2t[128 * 1024];          // [n][k] = W2[k][n]

__device__ __forceinline__ uint32_t tanh2_fast(uint32_t x2) {   // half2 tanh
    uint32_t r; asm("tanh.approx.f16x2 %0, %1;" : "=r"(r) : "r"(x2)); return r;
}

__device__ __forceinline__ void mma_f16(float* c, const uint32_t* a, const uint32_t* b) {
    asm volatile("mma.sync.aligned.m16n8k16.row.col.f32.f16.f16.f32 "
        "{%0,%1,%2,%3}, {%4,%5,%6,%7}, {%8,%9}, {%0,%1,%2,%3};"
        : "+f"(c[0]), "+f"(c[1]), "+f"(c[2]), "+f"(c[3])
        : "r"(a[0]), "r"(a[1]), "r"(a[2]), "r"(a[3]), "r"(b[0]), "r"(b[1]));
}

__device__ __forceinline__ void ldsm4(uint32_t* r, uint32_t saddr) {
    asm volatile("ldmatrix.sync.aligned.m8n8.x4.shared.b16 {%0,%1,%2,%3}, [%4];"
        : "=r"(r[0]), "=r"(r[1]), "=r"(r[2]), "=r"(r[3]) : "r"(saddr));
}

__device__ __forceinline__ uint32_t smem_u32(const void* p) {
    return (uint32_t)__cvta_generic_to_shared(p);
}

__device__ __forceinline__ void cp16(void* sdst, const void* gsrc) {
    uint32_t s = (uint32_t)__cvta_generic_to_shared(sdst);
    asm volatile("cp.async.cg.shared.global [%0], [%1], 16;" :: "r"(s), "l"(gsrc) : "memory");
}
#define CP_COMMIT() asm volatile("cp.async.commit_group;" ::: "memory")
#define CP_WAIT0()  asm volatile("cp.async.wait_group 0;" ::: "memory")

// ---------------------------------------------------------------------------
// Prep kernels
// ---------------------------------------------------------------------------
__global__ __launch_bounds__(256) void prep_split(const float* __restrict__ enc,
                                                  const float* __restrict__ dec) {
    int i = blockIdx.x * 256 + threadIdx.x;
    if (i < 2048 * 512) {
        float x = enc[i];
        __half h = __float2half_rn(x);
        g_enc_hi[i] = h;
        g_enc_lo[i] = __float2half_rn(x - __half2float(h));
    }
    if (i < 512 * 512) {
        float x = dec[i];
        __half h = __float2half_rn(x);
        g_dec_hi[i] = h;
        g_dec_lo[i] = __float2half_rn(x - __half2float(h));
    }
}

__global__ __launch_bounds__(256) void prep_w1t(const float* __restrict__ W1) {
    __shared__ float tile[32][33];
    int tx = threadIdx.x & 31, ty = threadIdx.x >> 5;
    int bx = blockIdx.x & 31;        // n tile
    int by = blockIdx.x >> 5;        // k tile
    #pragma unroll
    for (int r = 0; r < 4; r++)
        tile[ty + r * 8][tx] = W1[(by * 32 + ty + r * 8) * 1024 + bx * 32 + tx];
    __syncthreads();
    #pragma unroll
    for (int r = 0; r < 4; r++) {
        int n  = bx * 32 + ty + r * 8;
        int kk = by * 32 + tx;
        float x = tile[tx][ty + r * 8];
        int p = kk >> 9;
        int idx = (p * 1024 + n) * 512 + (kk & 511);
        __half h = __float2half_rn(x);
        g_w1t_hi[idx] = h;
        g_w1t_lo[idx] = __float2half_rn(x - __half2float(h));
    }
}

__global__ __launch_bounds__(256) void prep_w2t(const float* __restrict__ W2) {
    __shared__ float tile[32][33];
    int tx = threadIdx.x & 31, ty = threadIdx.x >> 5;
    int bx = blockIdx.x & 3;          // n tile
    int by = blockIdx.x >> 2;         // k tile
    #pragma unroll
    for (int r = 0; r < 4; r++)
        tile[ty + r * 8][tx] = W2[(by * 32 + ty + r * 8) * 128 + bx * 32 + tx];
    __syncthreads();
    #pragma unroll
    for (int r = 0; r < 4; r++) {
        int n = bx * 32 + ty + r * 8;
        int k = by * 32 + tx;
        g_w2t[n * 1024 + k] = __float2half(tile[tx][ty + r * 8]);
    }
}

// ---------------------------------------------------------------------------
// Projection: C tile [128 x 64] = A[128x512] @ Wt[64x512]^T  (fp16 hi/lo x3)
// 320 CTAs: 0..255 enc, 256..319 dec (+b1). cp.async double-buffered, occ 3.
// Fragment loads via ldmatrix.x4. Rows padded to 40 halves (80B).
// ---------------------------------------------------------------------------
#define PROJ_BUF 30720
#define PROJ_SMEM (2 * PROJ_BUF)

__global__ __launch_bounds__(256, 3) void proj_kernel(const float* __restrict__ b1) {
    extern __shared__ char smem[];
    uint32_t sb = smem_u32(smem);

    int tid = threadIdx.x, wid = tid >> 5, lane = tid & 31;
    int gq = lane >> 2, tg = lane & 3;

    int id = blockIdx.x;
    bool isdec = id >= 256;
    int lid2 = isdec ? id - 256 : id;
    int tile_m = lid2 >> 4, tile_n = lid2 & 15;
    int m0 = tile_m * 128, n0 = tile_n * 64;

    const char* Ahi = (const char*)(isdec ? g_dec_hi : g_enc_hi);
    const char* Alo = (const char*)(isdec ? g_dec_lo : g_enc_lo);
    const char* Bhi = (const char*)(g_w1t_hi + (isdec ? 1024 * 512 : 0));
    const char* Blo = (const char*)(g_w1t_lo + (isdec ? 1024 * 512 : 0));
    float* Cout = isdec ? g_dp : g_ep;

    // ldmatrix per-lane offsets (bytes within a tile region)
    // A frag (m16k16 @ rb,kk): m0=(rb,kk) m1=(rb+8,kk) m2=(rb,kk+8) m3=(rb+8,kk+8)
    uint32_t aOff = (uint32_t)(wid * 16 + ((lane >> 3) & 1) * 8 + (lane & 7)) * 80
                  + ((lane >> 4) & 1) * 16;
    // B frag pair (nb=2p,2p+1 @ kk): m0=(n0p,kk) m1=(n0p,kk+8) m2=(n0p+8,kk) m3=(n0p+8,kk+8)
    uint32_t bOff = (uint32_t)(((lane >> 4) & 1) * 8 + (lane & 7)) * 80
                  + ((lane >> 3) & 1) * 16;

    auto issue = [&](int kc) {
        char* base = smem + (kc & 1) * PROJ_BUF;
        #pragma unroll
        for (int it = 0; it < 2; it++) {
            int i = tid + it * 256;
            int r = i >> 2, sg = i & 3;
            size_t gsrc = (size_t)(m0 + r) * 1024 + kc * 64 + sg * 16;
            cp16(base + r * 80 + sg * 16, Ahi + gsrc);
            cp16(base + 10240 + r * 80 + sg * 16, Alo + gsrc);
        }
        {
            int r = tid >> 2, sg = tid & 3;
            size_t gsrc = (size_t)(n0 + r) * 1024 + kc * 64 + sg * 16;
            cp16(base + 20480 + r * 80 + sg * 16, Bhi + gsrc);
            cp16(base + 25600 + r * 80 + sg * 16, Blo + gsrc);
        }
    };

    float c[8][4];
    #pragma unroll
    for (int j = 0; j < 8; j++)
        #pragma unroll
        for (int q = 0; q < 4; q++) c[j][q] = 0.f;

    issue(0);
    CP_COMMIT();

    for (int kc = 0; kc < 16; kc++) {
        CP_WAIT0();
        __syncthreads();
        if (kc + 1 < 16) { issue(kc + 1); CP_COMMIT(); }

        uint32_t base = sb + (kc & 1) * PROJ_BUF;

        #pragma unroll
        for (int ks = 0; ks < 2; ks++) {
            uint32_t ko = ks * 32;
            uint32_t aH[4], aL[4];
            ldsm4(aH, base + aOff + ko);
            ldsm4(aL, base + 10240 + aOff + ko);
            #pragma unroll
            for (int p = 0; p < 4; p++) {
                uint32_t bo = (uint32_t)p * (16 * 80);
                uint32_t bh[4], bl[4];
                ldsm4(bh, base + 20480 + bo + bOff + ko);
                ldsm4(bl, base + 25600 + bo + bOff + ko);
                mma_f16(c[2 * p],     aH, &bh[0]);
                mma_f16(c[2 * p],     aH, &bl[0]);
                mma_f16(c[2 * p],     aL, &bh[0]);
                mma_f16(c[2 * p + 1], aH, &bh[2]);
                mma_f16(c[2 * p + 1], aH, &bl[2]);
                mma_f16(c[2 * p + 1], aL, &bh[2]);
            }
        }
    }

    #pragma unroll
    for (int nb = 0; nb < 8; nb++) {
        int col = n0 + nb * 8 + tg * 2;
        float bb0 = 0.f, bb1 = 0.f;
        if (isdec) { bb0 = __ldg(b1 + col); bb1 = __ldg(b1 + col + 1); }
        int row = m0 + wid * 16 + gq;
        float2 v0 = make_float2(c[nb][0] + bb0, c[nb][1] + bb1);
        float2 v1 = make_float2(c[nb][2] + bb0, c[nb][3] + bb1);
        *(float2*)(Cout + (size_t)row * 1024 + col) = v0;
        *(float2*)(Cout + (size_t)(row + 8) * 1024 + col) = v1;
    }
}

// ---------------------------------------------------------------------------
// Fused kernel: CTA = (batch b, 4 t, 64 u) -> M=256 rows x N=128, K=1024/64.
// Warp w (8 warps): rows w*32..w*32+31 (mt=2), all 128 n. A = tanh(ep+dp)
// generated into fragments; B frags via ldmatrix.x4 batched ahead of MMAs.
// smem: Bs 2x[128][72]h (36864) | dps 2x[64][72]f (36864) | sep [4][1024]f (16384)
// ---------------------------------------------------------------------------
#define FB_BS    0
#define FB_DPS   36864
#define FB_SEP   73728
#define FUSED_SMEM (73728 + 16384)

__global__ __launch_bounds__(256, 1) void fused_kernel(float* __restrict__ out,
                                                       const float* __restrict__ b2) {
    extern __shared__ char smem[];
    __half* Bs  = (__half*)(smem + FB_BS);     // [2][128][72]
    float*  dps = (float*)(smem + FB_DPS);     // [2][64][72]
    float*  sep = (float*)(smem + FB_SEP);     // [4][1024]

    int tid = threadIdx.x, wid = tid >> 5, lane = tid & 31;
    int gq = lane >> 2, tg = lane & 3;

    int b  = blockIdx.x >> 6;
    int tp = blockIdx.x & 63;
    int t0 = tp * 4;

    // stage ep (4 x 1024 f32) once
    #pragma unroll
    for (int it = 0; it < 4; it++) {
        int i = tid + it * 256;
        int r = i >> 8, k = (i & 255) * 4;
        *(float4*)&sep[r * 1024 + k] =
            *(const float4*)(g_ep + (size_t)(b * 256 + t0 + r) * 1024 + k);
    }

    auto issue = [&](int kc) {
        int buf = kc & 1;
        #pragma unroll
        for (int it = 0; it < 4; it++) {     // Bs: 1024 segs of 16B
            int i = tid + it * 256;
            int r = i >> 3, sg = i & 7;
            cp16((char*)Bs + buf * 18432 + r * 144 + sg * 16,
                 (const char*)g_w2t + (size_t)r * 2048 + kc * 128 + sg * 16);
        }
        #pragma unroll
        for (int it = 0; it < 4; it++) {     // dps: 1024 segs of 16B
            int i = tid + it * 256;
            int u = i >> 4, sg = i & 15;
            cp16((char*)dps + buf * 18432 + u * 288 + sg * 16,
                 (const char*)g_dp + (size_t)(b * 64 + u) * 4096 + kc * 256 + sg * 16);
        }
    };

    int tl = wid >> 1;                 // t_local of this warp's 32 rows
    int u0 = (wid & 1) * 32 + gq;      // u of frag-row gq in mt=0 tile

    // ldmatrix lane offsets for B frag pairs: pair p -> nb=2p, 2p+1
    // m0=(n:p*16..+7, k) m1=(same n, k+8) m2=(n+8, k) m3=(n+8, k+8)
    uint32_t BsAddr = smem_u32(Bs);
    uint32_t bLane = (uint32_t)(((lane >> 4) & 1) * 8 + (lane & 7)) * 144
                   + ((lane >> 3) & 1) * 16;
    uint32_t baddr[8];
    #pragma unroll
    for (int p = 0; p < 8; p++) baddr[p] = BsAddr + (uint32_t)p * (16 * 144) + bLane;

    float c[2][16][4];
    #pragma unroll
    for (int i = 0; i < 2; i++)
        #pragma unroll
        for (int j = 0; j < 16; j++)
            #pragma unroll
            for (int q = 0; q < 4; q++) c[i][j][q] = 0.f;

    issue(0);
    CP_COMMIT();

    for (int kc = 0; kc < 16; kc++) {
        CP_WAIT0();
        __syncthreads();
        if (kc + 1 < 16) { issue(kc + 1); CP_COMMIT(); }

        int buf = kc & 1;
        const float* ept = sep + tl * 1024 + kc * 64;
        const float* dpb = dps + buf * 4608;
        uint32_t bufoff = (uint32_t)buf * 18432;

        #pragma unroll
        for (int ks = 0; ks < 4; ks++) {
            // 1) batch all B fragment loads for this k-step
            uint32_t br[32];
            #pragma unroll
            for (int p = 0; p < 8; p++)
                ldsm4(&br[p * 4], baddr[p] + bufoff + ks * 32);

            // 2) generate A fragments (covers LDSM latency)
            uint32_t areg[2][4];
            #pragma unroll
            for (int kp = 0; kp < 2; kp++) {
                int k = ks * 16 + tg * 2 + kp * 8;
                float2 e = *(const float2*)(ept + k);
                #pragma unroll
                for (int mt = 0; mt < 2; mt++) {
                    int u = u0 + mt * 16;
                    float2 da = *(const float2*)(dpb + u * 72 + k);
                    float2 db = *(const float2*)(dpb + (u + 8) * 72 + k);
                    __half2 ha = __floats2half2_rn(e.x + da.x, e.y + da.y);
                    __half2 hb = __floats2half2_rn(e.x + db.x, e.y + db.y);
                    areg[mt][kp * 2 + 0] = tanh2_fast(*(uint32_t*)&ha);
                    areg[mt][kp * 2 + 1] = tanh2_fast(*(uint32_t*)&hb);
                }
            }

            // 3) MMAs (B frags reused across both mt tiles)
            #pragma unroll
            for (int nb = 0; nb < 16; nb++) {
                mma_f16(c[0][nb], areg[0], &br[nb * 2]);
                mma_f16(c[1][nb], areg[1], &br[nb * 2]);
            }
        }
    }

    // epilogue: global row = b*16384 + t0*64 + local (contiguous)
    size_t orow0 = (size_t)b * 16384 + (size_t)t0 * 64;
    #pragma unroll
    for (int mt = 0; mt < 2; mt++) {
        int row0 = wid * 32 + mt * 16 + gq;
        #pragma unroll
        for (int nb = 0; nb < 16; nb++) {
            int col = nb * 8 + tg * 2;
            float bb0 = __ldg(b2 + col);
            float bb1 = __ldg(b2 + col + 1);
            float2 v0 = make_float2(c[mt][nb][0] + bb0, c[mt][nb][1] + bb1);
            float2 v1 = make_float2(c[mt][nb][2] + bb0, c[mt][nb][3] + bb1);
            *(float2*)(out + (orow0 + row0) * 128 + col) = v0;
            *(float2*)(out + (orow0 + row0 + 8) * 128 + col) = v1;
        }
    }
}

// ---------------------------------------------------------------------------
extern "C" void kernel_launch(void* const* d_in, const int* in_sizes, int n_in,
                              void* d_out, int out_size) {
    const float* enc = (const float*)d_in[0];
    const float* dec = (const float*)d_in[1];
    const float* W1  = (const float*)d_in[2];
    const float* b1  = (const float*)d_in[3];
    const float* W2  = (const float*)d_in[4];
    const float* b2  = (const float*)d_in[5];
    float* out = (float*)d_out;

    cudaFuncSetAttribute(proj_kernel,  cudaFuncAttributeMaxDynamicSharedMemorySize, PROJ_SMEM);
    cudaFuncSetAttribute(fused_kernel, cudaFuncAttributeMaxDynamicSharedMemorySize, FUSED_SMEM);

    prep_split<<<4096, 256>>>(enc, dec);
    prep_w1t<<<1024, 256>>>(W1);
    prep_w2t<<<128, 256>>>(W2);
    proj_kernel<<<320, 256, PROJ_SMEM>>>(b1);
    fused_kernel<<<512, 256, FUSED_SMEM>>>(out, b2);
}

// round 8
// speedup vs baseline: 2.1731x; 1.0237x over previous
#include <cuda_runtime.h>
#include <cuda_fp16.h>
#include <stdint.h>

// ---------------------------------------------------------------------------
// out[b,t,u,o] = sum_h tanh(ep[b,t,h] + dp[b,u,h]) * W2[h,o] + b2[o]
//   ep = enc @ W1[:512],  dp = dec @ W1[512:] + b1
// enc (8,256,512) dec (8,64,512) W1 (1024,1024) b1 (1024) W2 (1024,128) b2 (128)
// out (8,256,64,128) fp32.  Base ISA only (mma.sync + cp.async + ldmatrix).
// ---------------------------------------------------------------------------

__device__ float   g_ep[2048 * 1024];          // enc proj fp32
__device__ float   g_dp[512 * 1024];           // dec proj + b1 fp32
__device__ __half  g_enc_hi[2048 * 512];
__device__ __half  g_enc_lo[2048 * 512];
__device__ __half  g_dec_hi[512 * 512];
__device__ __half  g_dec_lo[512 * 512];
__device__ __half  g_w1t_hi[2 * 1024 * 512];   // [part][n][k]
__device__ __half  g_w1t_lo[2 * 1024 * 512];
__device__ __half  g_w2t[128 * 1024];          // [n][k] = W2[k][n]

__device__ __forceinline__ uint32_t tanh2_fast(uint32_t x2) {   // half2 tanh
    uint32_t r; asm("tanh.approx.f16x2 %0, %1;" : "=r"(r) : "r"(x2)); return r;
}

__device__ __forceinline__ void mma_f16(float* c, const uint32_t* a, const uint32_t* b) {
    asm volatile("mma.sync.aligned.m16n8k16.row.col.f32.f16.f16.f32 "
        "{%0,%1,%2,%3}, {%4,%5,%6,%7}, {%8,%9}, {%0,%1,%2,%3};"
        : "+f"(c[0]), "+f"(c[1]), "+f"(c[2]), "+f"(c[3])
        : "r"(a[0]), "r"(a[1]), "r"(a[2]), "r"(a[3]), "r"(b[0]), "r"(b[1]));
}

__device__ __forceinline__ void ldsm4(uint32_t* r, uint32_t saddr) {
    asm volatile("ldmatrix.sync.aligned.m8n8.x4.shared.b16 {%0,%1,%2,%3}, [%4];"
        : "=r"(r[0]), "=r"(r[1]), "=r"(r[2]), "=r"(r[3]) : "r"(saddr));
}

__device__ __forceinline__ uint32_t smem_u32(const void* p) {
    return (uint32_t)__cvta_generic_to_shared(p);
}

__device__ __forceinline__ void cp16(void* sdst, const void* gsrc) {
    uint32_t s = (uint32_t)__cvta_generic_to_shared(sdst);
    asm volatile("cp.async.cg.shared.global [%0], [%1], 16;" :: "r"(s), "l"(gsrc) : "memory");
}
#define CP_COMMIT() asm volatile("cp.async.commit_group;" ::: "memory")
#define CP_WAIT0()  asm volatile("cp.async.wait_group 0;" ::: "memory")

// ---------------------------------------------------------------------------
// Prep kernels
// ---------------------------------------------------------------------------
__global__ __launch_bounds__(256) void prep_split(const float* __restrict__ enc,
                                                  const float* __restrict__ dec) {
    int i = blockIdx.x * 256 + threadIdx.x;
    if (i < 2048 * 512) {
        float x = enc[i];
        __half h = __float2half_rn(x);
        g_enc_hi[i] = h;
        g_enc_lo[i] = __float2half_rn(x - __half2float(h));
    }
    if (i < 512 * 512) {
        float x = dec[i];
        __half h = __float2half_rn(x);
        g_dec_hi[i] = h;
        g_dec_lo[i] = __float2half_rn(x - __half2float(h));
    }
}

__global__ __launch_bounds__(256) void prep_w1t(const float* __restrict__ W1) {
    __shared__ float tile[32][33];
    int tx = threadIdx.x & 31, ty = threadIdx.x >> 5;
    int bx = blockIdx.x & 31;        // n tile
    int by = blockIdx.x >> 5;        // k tile
    #pragma unroll
    for (int r = 0; r < 4; r++)
        tile[ty + r * 8][tx] = W1[(by * 32 + ty + r * 8) * 1024 + bx * 32 + tx];
    __syncthreads();
    #pragma unroll
    for (int r = 0; r < 4; r++) {
        int n  = bx * 32 + ty + r * 8;
        int kk = by * 32 + tx;
        float x = tile[tx][ty + r * 8];
        int p = kk >> 9;
        int idx = (p * 1024 + n) * 512 + (kk & 511);
        __half h = __float2half_rn(x);
        g_w1t_hi[idx] = h;
        g_w1t_lo[idx] = __float2half_rn(x - __half2float(h));
    }
}

__global__ __launch_bounds__(256) void prep_w2t(const float* __restrict__ W2) {
    __shared__ float tile[32][33];
    int tx = threadIdx.x & 31, ty = threadIdx.x >> 5;
    int bx = blockIdx.x & 3;          // n tile
    int by = blockIdx.x >> 2;         // k tile
    #pragma unroll
    for (int r = 0; r < 4; r++)
        tile[ty + r * 8][tx] = W2[(by * 32 + ty + r * 8) * 128 + bx * 32 + tx];
    __syncthreads();
    #pragma unroll
    for (int r = 0; r < 4; r++) {
        int n = bx * 32 + ty + r * 8;
        int k = by * 32 + tx;
        g_w2t[n * 1024 + k] = __float2half(tile[tx][ty + r * 8]);
    }
}

// ---------------------------------------------------------------------------
// Projection: C tile [128 x 64] = A[128x512] @ Wt[64x512]^T  (fp16 hi/lo x3)
// 320 CTAs: 0..255 enc, 256..319 dec (+b1). cp.async double-buffered, occ 3.
// Fragment loads via ldmatrix.x4. Rows padded to 40 halves (80B).
// ---------------------------------------------------------------------------
#define PROJ_BUF 30720
#define PROJ_SMEM (2 * PROJ_BUF)

__global__ __launch_bounds__(256, 3) void proj_kernel(const float* __restrict__ b1) {
    extern __shared__ char smem[];
    uint32_t sb = smem_u32(smem);

    int tid = threadIdx.x, wid = tid >> 5, lane = tid & 31;
    int gq = lane >> 2, tg = lane & 3;

    int id = blockIdx.x;
    bool isdec = id >= 256;
    int lid2 = isdec ? id - 256 : id;
    int tile_m = lid2 >> 4, tile_n = lid2 & 15;
    int m0 = tile_m * 128, n0 = tile_n * 64;

    const char* Ahi = (const char*)(isdec ? g_dec_hi : g_enc_hi);
    const char* Alo = (const char*)(isdec ? g_dec_lo : g_enc_lo);
    const char* Bhi = (const char*)(g_w1t_hi + (isdec ? 1024 * 512 : 0));
    const char* Blo = (const char*)(g_w1t_lo + (isdec ? 1024 * 512 : 0));
    float* Cout = isdec ? g_dp : g_ep;

    uint32_t aOff = (uint32_t)(wid * 16 + ((lane >> 3) & 1) * 8 + (lane & 7)) * 80
                  + ((lane >> 4) & 1) * 16;
    uint32_t bOff = (uint32_t)(((lane >> 4) & 1) * 8 + (lane & 7)) * 80
                  + ((lane >> 3) & 1) * 16;

    auto issue = [&](int kc) {
        char* base = smem + (kc & 1) * PROJ_BUF;
        #pragma unroll
        for (int it = 0; it < 2; it++) {
            int i = tid + it * 256;
            int r = i >> 2, sg = i & 3;
            size_t gsrc = (size_t)(m0 + r) * 1024 + kc * 64 + sg * 16;
            cp16(base + r * 80 + sg * 16, Ahi + gsrc);
            cp16(base + 10240 + r * 80 + sg * 16, Alo + gsrc);
        }
        {
            int r = tid >> 2, sg = tid & 3;
            size_t gsrc = (size_t)(n0 + r) * 1024 + kc * 64 + sg * 16;
            cp16(base + 20480 + r * 80 + sg * 16, Bhi + gsrc);
            cp16(base + 25600 + r * 80 + sg * 16, Blo + gsrc);
        }
    };

    float c[8][4];
    #pragma unroll
    for (int j = 0; j < 8; j++)
        #pragma unroll
        for (int q = 0; q < 4; q++) c[j][q] = 0.f;

    issue(0);
    CP_COMMIT();

    for (int kc = 0; kc < 16; kc++) {
        CP_WAIT0();
        __syncthreads();
        if (kc + 1 < 16) { issue(kc + 1); CP_COMMIT(); }

        uint32_t base = sb + (kc & 1) * PROJ_BUF;

        #pragma unroll
        for (int ks = 0; ks < 2; ks++) {
            uint32_t ko = ks * 32;
            uint32_t aH[4], aL[4];
            ldsm4(aH, base + aOff + ko);
            ldsm4(aL, base + 10240 + aOff + ko);
            #pragma unroll
            for (int p = 0; p < 4; p++) {
                uint32_t bo = (uint32_t)p * (16 * 80);
                uint32_t bh[4], bl[4];
                ldsm4(bh, base + 20480 + bo + bOff + ko);
                ldsm4(bl, base + 25600 + bo + bOff + ko);
                mma_f16(c[2 * p],     aH, &bh[0]);
                mma_f16(c[2 * p],     aH, &bl[0]);
                mma_f16(c[2 * p],     aL, &bh[0]);
                mma_f16(c[2 * p + 1], aH, &bh[2]);
                mma_f16(c[2 * p + 1], aH, &bl[2]);
                mma_f16(c[2 * p + 1], aL, &bh[2]);
            }
        }
    }

    #pragma unroll
    for (int nb = 0; nb < 8; nb++) {
        int col = n0 + nb * 8 + tg * 2;
        float bb0 = 0.f, bb1 = 0.f;
        if (isdec) { bb0 = __ldg(b1 + col); bb1 = __ldg(b1 + col + 1); }
        int row = m0 + wid * 16 + gq;
        float2 v0 = make_float2(c[nb][0] + bb0, c[nb][1] + bb1);
        float2 v1 = make_float2(c[nb][2] + bb0, c[nb][3] + bb1);
        *(float2*)(Cout + (size_t)row * 1024 + col) = v0;
        *(float2*)(Cout + (size_t)(row + 8) * 1024 + col) = v1;
    }
}

// ---------------------------------------------------------------------------
// Fused kernel: CTA = (batch b, 2 t, 64 u) -> M=128 rows x N=128, K=1024/64.
// Warp w (8 warps): rows w*16..w*16+15, all 128 n.  occ 2 for latency hiding.
// A = tanh(ep+dp) into fragments; B frags pairwise ldmatrix with 1-pair prefetch.
// smem per CTA: Bs 2x[128][72]h (36864) | dps 2x[64][72]f (36864) | sep [2][1024]f (8192)
// total 81920 B -> 2 CTAs/SM.
// ---------------------------------------------------------------------------
#define FB_BS    0
#define FB_DPS   36864
#define FB_SEP   73728
#define FUSED_SMEM (73728 + 8192)

__global__ __launch_bounds__(256, 2) void fused_kernel(float* __restrict__ out,
                                                       const float* __restrict__ b2) {
    extern __shared__ char smem[];
    __half* Bs  = (__half*)(smem + FB_BS);     // [2][128][72]
    float*  dps = (float*)(smem + FB_DPS);     // [2][64][72]
    float*  sep = (float*)(smem + FB_SEP);     // [2][1024]

    int tid = threadIdx.x, wid = tid >> 5, lane = tid & 31;
    int gq = lane >> 2, tg = lane & 3;

    int b  = blockIdx.x >> 7;
    int tp = blockIdx.x & 127;
    int t0 = tp * 2;

    // stage ep (2 x 1024 f32) once
    #pragma unroll
    for (int it = 0; it < 2; it++) {
        int i = tid + it * 256;
        int r = i >> 8, k = (i & 255) * 4;
        *(float4*)&sep[r * 1024 + k] =
            *(const float4*)(g_ep + (size_t)(b * 256 + t0 + r) * 1024 + k);
    }

    auto issue = [&](int kc) {
        int buf = kc & 1;
        #pragma unroll
        for (int it = 0; it < 4; it++) {     // Bs: 1024 segs of 16B
            int i = tid + it * 256;
            int r = i >> 3, sg = i & 7;
            cp16((char*)Bs + buf * 18432 + r * 144 + sg * 16,
                 (const char*)g_w2t + (size_t)r * 2048 + kc * 128 + sg * 16);
        }
        #pragma unroll
        for (int it = 0; it < 4; it++) {     // dps: 1024 segs of 16B
            int i = tid + it * 256;
            int u = i >> 4, sg = i & 15;
            cp16((char*)dps + buf * 18432 + u * 288 + sg * 16,
                 (const char*)g_dp + (size_t)(b * 64 + u) * 4096 + kc * 256 + sg * 16);
        }
    };

    int tl = wid >> 2;                 // t_local of this warp's 16 rows
    int u0 = (wid & 3) * 16 + gq;      // u of frag-row gq

    uint32_t BsAddr = smem_u32(Bs);
    uint32_t bLane = (uint32_t)(((lane >> 4) & 1) * 8 + (lane & 7)) * 144
                   + ((lane >> 3) & 1) * 16;
    uint32_t baddr[8];
    #pragma unroll
    for (int p = 0; p < 8; p++) baddr[p] = BsAddr + (uint32_t)p * (16 * 144) + bLane;

    float c[16][4];
    #pragma unroll
    for (int j = 0; j < 16; j++)
        #pragma unroll
        for (int q = 0; q < 4; q++) c[j][q] = 0.f;

    issue(0);
    CP_COMMIT();

    for (int kc = 0; kc < 16; kc++) {
        CP_WAIT0();
        __syncthreads();
        if (kc + 1 < 16) { issue(kc + 1); CP_COMMIT(); }

        int buf = kc & 1;
        const float* ept = sep + tl * 1024 + kc * 64;
        const float* dpb = dps + buf * 4608;
        uint32_t bufoff = (uint32_t)buf * 18432;

        #pragma unroll
        for (int ks = 0; ks < 4; ks++) {
            // prefetch first B pair
            uint32_t br[2][4];
            ldsm4(br[0], baddr[0] + bufoff + ks * 32);

            // generate A fragments (covers LDSM latency)
            uint32_t areg[4];
            #pragma unroll
            for (int kp = 0; kp < 2; kp++) {
                int k = ks * 16 + tg * 2 + kp * 8;
                float2 e  = *(const float2*)(ept + k);
                float2 da = *(const float2*)(dpb + u0 * 72 + k);
                float2 db = *(const float2*)(dpb + (u0 + 8) * 72 + k);
                __half2 ha = __floats2half2_rn(e.x + da.x, e.y + da.y);
                __half2 hb = __floats2half2_rn(e.x + db.x, e.y + db.y);
                areg[kp * 2 + 0] = tanh2_fast(*(uint32_t*)&ha);
                areg[kp * 2 + 1] = tanh2_fast(*(uint32_t*)&hb);
            }

            // MMAs with one-pair-ahead B prefetch
            #pragma unroll
            for (int p = 0; p < 8; p++) {
                if (p < 7) ldsm4(br[(p + 1) & 1], baddr[p + 1] + bufoff + ks * 32);
                mma_f16(c[2 * p],     areg, &br[p & 1][0]);
                mma_f16(c[2 * p + 1], areg, &br[p & 1][2]);
            }
        }
    }

    // epilogue: global row = b*16384 + t0*64 + local (contiguous 128 rows)
    size_t orow0 = (size_t)b * 16384 + (size_t)t0 * 64;
    int row0 = wid * 16 + gq;
    #pragma unroll
    for (int nb = 0; nb < 16; nb++) {
        int col = nb * 8 + tg * 2;
        float bb0 = __ldg(b2 + col);
        float bb1 = __ldg(b2 + col + 1);
        float2 v0 = make_float2(c[nb][0] + bb0, c[nb][1] + bb1);
        float2 v1 = make_float2(c[nb][2] + bb0, c[nb][3] + bb1);
        *(float2*)(out + (orow0 + row0) * 128 + col) = v0;
        *(float2*)(out + (orow0 + row0 + 8) * 128 + col) = v1;
    }
}

// ---------------------------------------------------------------------------
extern "C" void kernel_launch(void* const* d_in, const int* in_sizes, int n_in,
                              void* d_out, int out_size) {
    const float* enc = (const float*)d_in[0];
    const float* dec = (const float*)d_in[1];
    const float* W1  = (const float*)d_in[2];
    const float* b1  = (const float*)d_in[3];
    const float* W2  = (const float*)d_in[4];
    const float* b2  = (const float*)d_in[5];
    float* out = (float*)d_out;

    cudaFuncSetAttribute(proj_kernel,  cudaFuncAttributeMaxDynamicSharedMemorySize, PROJ_SMEM);
    cudaFuncSetAttribute(fused_kernel, cudaFuncAttributeMaxDynamicSharedMemorySize, FUSED_SMEM);

    prep_split<<<4096, 256>>>(enc, dec);
    prep_w1t<<<1024, 256>>>(W1);
    prep_w2t<<<128, 256>>>(W2);
    proj_kernel<<<320, 256, PROJ_SMEM>>>(b1);
    fused_kernel<<<1024, 256, FUSED_SMEM>>>(out, b2);
}

// round 9
// speedup vs baseline: 2.2046x; 1.0145x over previous
#include <cuda_runtime.h>
#include <cuda_fp16.h>
#include <stdint.h>

// ---------------------------------------------------------------------------
// out[b,t,u,o] = sum_h tanh(ep[b,t,h] + dp[b,u,h]) * W2[h,o] + b2[o]
//   ep = enc @ W1[:512],  dp = dec @ W1[512:] + b1
// enc (8,256,512) dec (8,64,512) W1 (1024,1024) b1 (1024) W2 (1024,128) b2 (128)
// out (8,256,64,128) fp32.  Base ISA only (mma.sync + cp.async + ldmatrix).
// ---------------------------------------------------------------------------

__device__ float   g_ep[2048 * 1024];          // enc proj fp32
__device__ __half  g_dph[512 * 1024];          // dec proj + b1, fp16
__device__ __half  g_enc_hi[2048 * 512];
__device__ __half  g_enc_lo[2048 * 512];
__device__ __half  g_dec_hi[512 * 512];
__device__ __half  g_dec_lo[512 * 512];
__device__ __half  g_w1t_hi[2 * 1024 * 512];   // [part][n][k]
__device__ __half  g_w1t_lo[2 * 1024 * 512];
__device__ __half  g_w2t[128 * 1024];          // [n][k] = W2[k][n]

__device__ __forceinline__ uint32_t tanh2_fast(uint32_t x2) {   // half2 tanh
    uint32_t r; asm("tanh.approx.f16x2 %0, %1;" : "=r"(r) : "r"(x2)); return r;
}

__device__ __forceinline__ void mma_f16(float* c, const uint32_t* a, const uint32_t* b) {
    asm volatile("mma.sync.aligned.m16n8k16.row.col.f32.f16.f16.f32 "
        "{%0,%1,%2,%3}, {%4,%5,%6,%7}, {%8,%9}, {%0,%1,%2,%3};"
        : "+f"(c[0]), "+f"(c[1]), "+f"(c[2]), "+f"(c[3])
        : "r"(a[0]), "r"(a[1]), "r"(a[2]), "r"(a[3]), "r"(b[0]), "r"(b[1]));
}

__device__ __forceinline__ void ldsm4(uint32_t* r, uint32_t saddr) {
    asm volatile("ldmatrix.sync.aligned.m8n8.x4.shared.b16 {%0,%1,%2,%3}, [%4];"
        : "=r"(r[0]), "=r"(r[1]), "=r"(r[2]), "=r"(r[3]) : "r"(saddr));
}

__device__ __forceinline__ uint32_t smem_u32(const void* p) {
    return (uint32_t)__cvta_generic_to_shared(p);
}

__device__ __forceinline__ void cp16(void* sdst, const void* gsrc) {
    uint32_t s = (uint32_t)__cvta_generic_to_shared(sdst);
    asm volatile("cp.async.cg.shared.global [%0], [%1], 16;" :: "r"(s), "l"(gsrc) : "memory");
}
#define CP_COMMIT() asm volatile("cp.async.commit_group;" ::: "memory")
#define CP_WAIT0()  asm volatile("cp.async.wait_group 0;" ::: "memory")

// ---------------------------------------------------------------------------
// Merged prep kernel: blocks [0,4096): enc+dec hi/lo split; [4096,5120): W1^T;
// [5120,5248): W2^T fp16.
// ---------------------------------------------------------------------------
__global__ __launch_bounds__(256) void prep_all(const float* __restrict__ enc,
                                                const float* __restrict__ dec,
                                                const float* __restrict__ W1,
                                                const float* __restrict__ W2) {
    __shared__ float tile[32][33];
    int bid = blockIdx.x, tid = threadIdx.x;
    if (bid < 4096) {
        int i = bid * 256 + tid;
        {
            float x = enc[i];
            __half h = __float2half_rn(x);
            g_enc_hi[i] = h;
            g_enc_lo[i] = __float2half_rn(x - __half2float(h));
        }
        if (i < 512 * 512) {
            float x = dec[i];
            __half h = __float2half_rn(x);
            g_dec_hi[i] = h;
            g_dec_lo[i] = __float2half_rn(x - __half2float(h));
        }
    } else if (bid < 5120) {
        int blk = bid - 4096;
        int tx = tid & 31, ty = tid >> 5;
        int bx = blk & 31, by = blk >> 5;       // n tile, k tile
        #pragma unroll
        for (int r = 0; r < 4; r++)
            tile[ty + r * 8][tx] = W1[(by * 32 + ty + r * 8) * 1024 + bx * 32 + tx];
        __syncthreads();
        #pragma unroll
        for (int r = 0; r < 4; r++) {
            int n  = bx * 32 + ty + r * 8;
            int kk = by * 32 + tx;
            float x = tile[tx][ty + r * 8];
            int p = kk >> 9;
            int idx = (p * 1024 + n) * 512 + (kk & 511);
            __half h = __float2half_rn(x);
            g_w1t_hi[idx] = h;
            g_w1t_lo[idx] = __float2half_rn(x - __half2float(h));
        }
    } else {
        int blk = bid - 5120;
        int tx = tid & 31, ty = tid >> 5;
        int bx = blk & 3, by = blk >> 2;        // n tile, k tile
        #pragma unroll
        for (int r = 0; r < 4; r++)
            tile[ty + r * 8][tx] = W2[(by * 32 + ty + r * 8) * 128 + bx * 32 + tx];
        __syncthreads();
        #pragma unroll
        for (int r = 0; r < 4; r++) {
            int n = bx * 32 + ty + r * 8;
            int k = by * 32 + tx;
            g_w2t[n * 1024 + k] = __float2half(tile[tx][ty + r * 8]);
        }
    }
}

// ---------------------------------------------------------------------------
// Projection: C tile [128 x 64] = A[128x512] @ Wt[64x512]^T  (fp16 hi/lo x3)
// 320 CTAs: 0..255 enc -> g_ep (f32), 256..319 dec -> g_dph (fp16, +b1).
// Warps 4m x 2n, mt=2: warp = 32 rows x 32 cols.  cp.async double-buffered.
// Stage: AH[128x80B] AL BH[64x80B] BL = 30720 B; x2 stages.
// ---------------------------------------------------------------------------
#define PROJ_STAGE 30720
#define PROJ_SMEM (2 * PROJ_STAGE)

__global__ __launch_bounds__(256, 2) void proj_kernel(const float* __restrict__ b1) {
    extern __shared__ char smem[];
    uint32_t sb = smem_u32(smem);

    int tid = threadIdx.x, wid = tid >> 5, lane = tid & 31;
    int gq = lane >> 2, tg = lane & 3;
    int warp_m = wid >> 1, warp_n = wid & 1;

    int id = blockIdx.x;
    bool isdec = id >= 256;
    int lid2 = isdec ? id - 256 : id;
    int tile_m = lid2 >> 4, tile_n = lid2 & 15;
    int m0 = tile_m * 128, n0 = tile_n * 64;

    const char* Ahi = (const char*)(isdec ? g_dec_hi : g_enc_hi);
    const char* Alo = (const char*)(isdec ? g_dec_lo : g_enc_lo);
    const char* Bhi = (const char*)(g_w1t_hi + (isdec ? 1024 * 512 : 0));
    const char* Blo = (const char*)(g_w1t_lo + (isdec ? 1024 * 512 : 0));

    // ldmatrix per-lane offsets
    uint32_t aOff = (uint32_t)(warp_m * 32 + ((lane >> 3) & 1) * 8 + (lane & 7)) * 80
                  + ((lane >> 4) & 1) * 16;
    uint32_t bOff = (uint32_t)(warp_n * 32 + ((lane >> 4) & 1) * 8 + (lane & 7)) * 80
                  + ((lane >> 3) & 1) * 16;

    auto issue = [&](int kc) {
        char* base = smem + (kc & 1) * PROJ_STAGE;
        #pragma unroll
        for (int it = 0; it < 2; it++) {
            int i = tid + it * 256;          // 512: r=i>>2, sg=i&3
            int r = i >> 2, sg = i & 3;
            size_t gsrc = (size_t)(m0 + r) * 1024 + kc * 64 + sg * 16;
            cp16(base + r * 80 + sg * 16, Ahi + gsrc);
            cp16(base + 10240 + r * 80 + sg * 16, Alo + gsrc);
        }
        {
            int r = tid >> 2, sg = tid & 3;  // 64 rows x 4 segs
            size_t gsrc = (size_t)(n0 + r) * 1024 + kc * 64 + sg * 16;
            cp16(base + 20480 + r * 80 + sg * 16, Bhi + gsrc);
            cp16(base + 25600 + r * 80 + sg * 16, Blo + gsrc);
        }
    };

    float c[2][4][4];
    #pragma unroll
    for (int i = 0; i < 2; i++)
        #pragma unroll
        for (int j = 0; j < 4; j++)
            #pragma unroll
            for (int q = 0; q < 4; q++) c[i][j][q] = 0.f;

    issue(0);
    CP_COMMIT();

    for (int kc = 0; kc < 16; kc++) {
        CP_WAIT0();
        __syncthreads();
        if (kc + 1 < 16) { issue(kc + 1); CP_COMMIT(); }

        uint32_t base = sb + (kc & 1) * PROJ_STAGE;

        #pragma unroll
        for (int ks = 0; ks < 2; ks++) {
            uint32_t ko = ks * 32;
            uint32_t aH[2][4], aL[2][4];
            #pragma unroll
            for (int mt = 0; mt < 2; mt++) {
                ldsm4(aH[mt], base + aOff + mt * 1280 + ko);
                ldsm4(aL[mt], base + 10240 + aOff + mt * 1280 + ko);
            }
            #pragma unroll
            for (int p = 0; p < 2; p++) {
                uint32_t bh[4], bl[4];
                ldsm4(bh, base + 20480 + bOff + p * 1280 + ko);
                ldsm4(bl, base + 25600 + bOff + p * 1280 + ko);
                #pragma unroll
                for (int mt = 0; mt < 2; mt++) {
                    mma_f16(c[mt][2 * p],     aH[mt], &bh[0]);
                    mma_f16(c[mt][2 * p],     aH[mt], &bl[0]);
                    mma_f16(c[mt][2 * p],     aL[mt], &bh[0]);
                    mma_f16(c[mt][2 * p + 1], aH[mt], &bh[2]);
                    mma_f16(c[mt][2 * p + 1], aH[mt], &bl[2]);
                    mma_f16(c[mt][2 * p + 1], aL[mt], &bh[2]);
                }
            }
        }
    }

    // epilogue
    #pragma unroll
    for (int mt = 0; mt < 2; mt++) {
        #pragma unroll
        for (int nb = 0; nb < 4; nb++) {
            int col = n0 + warp_n * 32 + nb * 8 + tg * 2;
            int row = m0 + warp_m * 32 + mt * 16 + gq;
            if (!isdec) {
                float2 v0 = make_float2(c[mt][nb][0], c[mt][nb][1]);
                float2 v1 = make_float2(c[mt][nb][2], c[mt][nb][3]);
                *(float2*)(g_ep + (size_t)row * 1024 + col) = v0;
                *(float2*)(g_ep + (size_t)(row + 8) * 1024 + col) = v1;
            } else {
                float bb0 = __ldg(b1 + col), bb1 = __ldg(b1 + col + 1);
                __half2 h0 = __floats2half2_rn(c[mt][nb][0] + bb0, c[mt][nb][1] + bb1);
                __half2 h1 = __floats2half2_rn(c[mt][nb][2] + bb0, c[mt][nb][3] + bb1);
                *(__half2*)(g_dph + (size_t)row * 1024 + col) = h0;
                *(__half2*)(g_dph + (size_t)(row + 8) * 1024 + col) = h1;
            }
        }
    }
}

// ---------------------------------------------------------------------------
// Fused kernel: CTA = (batch b, 2 t, 64 u) -> M=128 rows x N=128, K=1024/64.
// Warps 4m x 2n, mt=2: warp = 32 rows x 64 cols.  occ 2.
// dp staged as fp16 (halves crossbar bytes); sum in f32 before half2 pack.
// smem: Bs 2x[128][72]h (36864) | dps 2x[64][72]h (18432) | sep [2][1024]f (8192)
// ---------------------------------------------------------------------------
#define FB_BS    0
#define FB_DPS   36864
#define FB_SEP   55296
#define FUSED_SMEM (55296 + 8192)

__global__ __launch_bounds__(256, 2) void fused_kernel(float* __restrict__ out,
                                                       const float* __restrict__ b2) {
    extern __shared__ char smem[];
    __half* Bs  = (__half*)(smem + FB_BS);     // [2][128][72]
    __half* dps = (__half*)(smem + FB_DPS);    // [2][64][72]
    float*  sep = (float*)(smem + FB_SEP);     // [2][1024]

    int tid = threadIdx.x, wid = tid >> 5, lane = tid & 31;
    int gq = lane >> 2, tg = lane & 3;
    int warp_m = wid >> 1, warp_n = wid & 1;

    int b  = blockIdx.x >> 7;
    int tp = blockIdx.x & 127;
    int t0 = tp * 2;

    // stage ep (2 x 1024 f32) once
    #pragma unroll
    for (int it = 0; it < 2; it++) {
        int i = tid + it * 256;
        int r = i >> 8, k = (i & 255) * 4;
        *(float4*)&sep[r * 1024 + k] =
            *(const float4*)(g_ep + (size_t)(b * 256 + t0 + r) * 1024 + k);
    }

    auto issue = [&](int kc) {
        int buf = kc & 1;
        #pragma unroll
        for (int it = 0; it < 4; it++) {     // Bs: 1024 segs of 16B
            int i = tid + it * 256;
            int r = i >> 3, sg = i & 7;
            cp16((char*)Bs + buf * 18432 + r * 144 + sg * 16,
                 (const char*)g_w2t + (size_t)r * 2048 + kc * 128 + sg * 16);
        }
        #pragma unroll
        for (int it = 0; it < 2; it++) {     // dps fp16: 512 segs of 16B
            int i = tid + it * 256;
            int u = i >> 3, sg = i & 7;
            cp16((char*)dps + buf * 9216 + u * 144 + sg * 16,
                 (const char*)g_dph + (size_t)(b * 64 + u) * 2048 + kc * 128 + sg * 16);
        }
    };

    int tl = warp_m >> 1;                 // t_local of this warp's rows
    int ub = (warp_m & 1) * 32;           // u base of this warp's rows

    uint32_t BsAddr = smem_u32(Bs);
    uint32_t bLane = (uint32_t)(((lane >> 4) & 1) * 8 + (lane & 7)) * 144
                   + ((lane >> 3) & 1) * 16;
    uint32_t baddr[4];
    #pragma unroll
    for (int p = 0; p < 4; p++)
        baddr[p] = BsAddr + (uint32_t)(warp_n * 64 + p * 16) * 144 + bLane;

    float c[2][8][4];
    #pragma unroll
    for (int i = 0; i < 2; i++)
        #pragma unroll
        for (int j = 0; j < 8; j++)
            #pragma unroll
            for (int q = 0; q < 4; q++) c[i][j][q] = 0.f;

    issue(0);
    CP_COMMIT();

    for (int kc = 0; kc < 16; kc++) {
        CP_WAIT0();
        __syncthreads();
        if (kc + 1 < 16) { issue(kc + 1); CP_COMMIT(); }

        int buf = kc & 1;
        const float*  ept = sep + tl * 1024 + kc * 64;
        const __half* dph = dps + buf * 4608;
        uint32_t bufoff = (uint32_t)buf * 18432;

        #pragma unroll
        for (int ks = 0; ks < 4; ks++) {
            // 1) batch B fragment loads (4 ldsm4 -> 8 n-tiles)
            uint32_t br[16];
            #pragma unroll
            for (int p = 0; p < 4; p++)
                ldsm4(&br[p * 4], baddr[p] + bufoff + ks * 32);

            // 2) A fragments: tanh(ep + dp), dp fp16 -> f32 sum -> half2
            uint32_t areg[2][4];
            #pragma unroll
            for (int kp = 0; kp < 2; kp++) {
                int k = ks * 16 + tg * 2 + kp * 8;
                float2 e = *(const float2*)(ept + k);
                #pragma unroll
                for (int mt = 0; mt < 2; mt++) {
                    int u = ub + mt * 16 + gq;
                    __half2 da = *(const __half2*)(dph + u * 72 + k);
                    __half2 db = *(const __half2*)(dph + (u + 8) * 72 + k);
                    float2 fa = __half22float2(da);
                    float2 fb = __half22float2(db);
                    __half2 ha = __floats2half2_rn(e.x + fa.x, e.y + fa.y);
                    __half2 hb = __floats2half2_rn(e.x + fb.x, e.y + fb.y);
                    areg[mt][kp * 2 + 0] = tanh2_fast(*(uint32_t*)&ha);
                    areg[mt][kp * 2 + 1] = tanh2_fast(*(uint32_t*)&hb);
                }
            }

            // 3) MMAs: B frags reused across both mt tiles
            #pragma unroll
            for (int p = 0; p < 4; p++) {
                mma_f16(c[0][2 * p],     areg[0], &br[p * 4 + 0]);
                mma_f16(c[0][2 * p + 1], areg[0], &br[p * 4 + 2]);
                mma_f16(c[1][2 * p],     areg[1], &br[p * 4 + 0]);
                mma_f16(c[1][2 * p + 1], areg[1], &br[p * 4 + 2]);
            }
        }
    }

    // epilogue: global row = b*16384 + t0*64 + local (contiguous 128 rows)
    size_t orow0 = (size_t)b * 16384 + (size_t)t0 * 64;
    #pragma unroll
    for (int mt = 0; mt < 2; mt++) {
        int row0 = warp_m * 32 + mt * 16 + gq;
        #pragma unroll
        for (int nb = 0; nb < 8; nb++) {
            int col = warp_n * 64 + nb * 8 + tg * 2;
            float bb0 = __ldg(b2 + col);
            float bb1 = __ldg(b2 + col + 1);
            float2 v0 = make_float2(c[mt][nb][0] + bb0, c[mt][nb][1] + bb1);
            float2 v1 = make_float2(c[mt][nb][2] + bb0, c[mt][nb][3] + bb1);
            *(float2*)(out + (orow0 + row0) * 128 + col) = v0;
            *(float2*)(out + (orow0 + row0 + 8) * 128 + col) = v1;
        }
    }
}

// ---------------------------------------------------------------------------
extern "C" void kernel_launch(void* const* d_in, const int* in_sizes, int n_in,
                              void* d_out, int out_size) {
    const float* enc = (const float*)d_in[0];
    const float* dec = (const float*)d_in[1];
    const float* W1  = (const float*)d_in[2];
    const float* b1  = (const float*)d_in[3];
    const float* W2  = (const float*)d_in[4];
    const float* b2  = (const float*)d_in[5];
    float* out = (float*)d_out;

    cudaFuncSetAttribute(proj_kernel,  cudaFuncAttributeMaxDynamicSharedMemorySize, PROJ_SMEM);
    cudaFuncSetAttribute(fused_kernel, cudaFuncAttributeMaxDynamicSharedMemorySize, FUSED_SMEM);

    prep_all<<<5248, 256>>>(enc, dec, W1, W2);
    proj_kernel<<<320, 256, PROJ_SMEM>>>(b1);
    fused_kernel<<<1024, 256, FUSED_SMEM>>>(out, b2);
}

// round 10
// speedup vs baseline: 2.5037x; 1.1357x over previous
#include <cuda_runtime.h>
#include <cuda_fp16.h>
#include <stdint.h>

// ---------------------------------------------------------------------------
// out[b,t,u,o] = sum_h tanh(ep[b,t,h] + dp[b,u,h]) * W2[h,o] + b2[o]
//   ep = enc @ W1[:512],  dp = dec @ W1[512:] + b1
// enc (8,256,512) dec (8,64,512) W1 (1024,1024) b1 (1024) W2 (1024,128) b2 (128)
// out (8,256,64,128) fp32.  Base ISA only (mma.sync + cp.async + ldmatrix).
// ---------------------------------------------------------------------------

__device__ float   g_ep[2048 * 1024];          // enc proj fp32
__device__ __half  g_dph[512 * 1024];          // dec proj + b1, fp16
__device__ __half  g_ench[2048 * 512];         // enc fp16 (single)
__device__ __half  g_dech[512 * 512];          // dec fp16 (single)
__device__ __half  g_w1t_hi[2 * 1024 * 512];   // [part][n][k]
__device__ __half  g_w1t_lo[2 * 1024 * 512];
__device__ __half  g_w2t[128 * 1024];          // [n][k] = W2[k][n]

__device__ __forceinline__ uint32_t tanh2_fast(uint32_t x2) {   // half2 tanh
    uint32_t r; asm("tanh.approx.f16x2 %0, %1;" : "=r"(r) : "r"(x2)); return r;
}

__device__ __forceinline__ void mma_f16(float* c, const uint32_t* a, const uint32_t* b) {
    asm volatile("mma.sync.aligned.m16n8k16.row.col.f32.f16.f16.f32 "
        "{%0,%1,%2,%3}, {%4,%5,%6,%7}, {%8,%9}, {%0,%1,%2,%3};"
        : "+f"(c[0]), "+f"(c[1]), "+f"(c[2]), "+f"(c[3])
        : "r"(a[0]), "r"(a[1]), "r"(a[2]), "r"(a[3]), "r"(b[0]), "r"(b[1]));
}

__device__ __forceinline__ void ldsm4(uint32_t* r, uint32_t saddr) {
    asm volatile("ldmatrix.sync.aligned.m8n8.x4.shared.b16 {%0,%1,%2,%3}, [%4];"
        : "=r"(r[0]), "=r"(r[1]), "=r"(r[2]), "=r"(r[3]) : "r"(saddr));
}

__device__ __forceinline__ uint32_t smem_u32(const void* p) {
    return (uint32_t)__cvta_generic_to_shared(p);
}

__device__ __forceinline__ void cp16(void* sdst, const void* gsrc) {
    uint32_t s = (uint32_t)__cvta_generic_to_shared(sdst);
    asm volatile("cp.async.cg.shared.global [%0], [%1], 16;" :: "r"(s), "l"(gsrc) : "memory");
}
#define CP_COMMIT() asm volatile("cp.async.commit_group;" ::: "memory")
#define CP_WAIT0()  asm volatile("cp.async.wait_group 0;" ::: "memory")

// ---------------------------------------------------------------------------
// Merged prep: blocks [0,1024): enc+dec fp16 (4 elems/thread);
// [1024,2048): W1^T hi/lo; [2048,2176): W2^T fp16.
// ---------------------------------------------------------------------------
__global__ __launch_bounds__(256) void prep_all(const float* __restrict__ enc,
                                                const float* __restrict__ dec,
                                                const float* __restrict__ W1,
                                                const float* __restrict__ W2) {
    __shared__ float tile[32][33];
    int bid = blockIdx.x, tid = threadIdx.x;
    if (bid < 1024) {
        int i = bid * 256 + tid;       // float4 index
        {
            float4 v = *(const float4*)(enc + (size_t)i * 4);
            __half2 h0 = __floats2half2_rn(v.x, v.y);
            __half2 h1 = __floats2half2_rn(v.z, v.w);
            *(uint2*)&g_ench[(size_t)i * 4] = make_uint2(*(uint32_t*)&h0, *(uint32_t*)&h1);
        }
        if (i < 65536) {
            float4 v = *(const float4*)(dec + (size_t)i * 4);
            __half2 h0 = __floats2half2_rn(v.x, v.y);
            __half2 h1 = __floats2half2_rn(v.z, v.w);
            *(uint2*)&g_dech[(size_t)i * 4] = make_uint2(*(uint32_t*)&h0, *(uint32_t*)&h1);
        }
    } else if (bid < 2048) {
        int blk = bid - 1024;
        int tx = tid & 31, ty = tid >> 5;
        int bx = blk & 31, by = blk >> 5;       // n tile, k tile
        #pragma unroll
        for (int r = 0; r < 4; r++)
            tile[ty + r * 8][tx] = W1[(by * 32 + ty + r * 8) * 1024 + bx * 32 + tx];
        __syncthreads();
        #pragma unroll
        for (int r = 0; r < 4; r++) {
            int n  = bx * 32 + ty + r * 8;
            int kk = by * 32 + tx;
            float x = tile[tx][ty + r * 8];
            int p = kk >> 9;
            int idx = (p * 1024 + n) * 512 + (kk & 511);
            __half h = __float2half_rn(x);
            g_w1t_hi[idx] = h;
            g_w1t_lo[idx] = __float2half_rn(x - __half2float(h));
        }
    } else {
        int blk = bid - 2048;
        int tx = tid & 31, ty = tid >> 5;
        int bx = blk & 3, by = blk >> 2;        // n tile, k tile
        #pragma unroll
        for (int r = 0; r < 4; r++)
            tile[ty + r * 8][tx] = W2[(by * 32 + ty + r * 8) * 128 + bx * 32 + tx];
        __syncthreads();
        #pragma unroll
        for (int r = 0; r < 4; r++) {
            int n = bx * 32 + ty + r * 8;
            int k = by * 32 + tx;
            g_w2t[n * 1024 + k] = __float2half(tile[tx][ty + r * 8]);
        }
    }
}

// ---------------------------------------------------------------------------
// Projection (2-term: aH*bH + aH*bL).  256 CTAs, single wave at occ 2.
// bids 0..127:   enc tile 256x64 -> g_ep   (8 warps x (32 rows x 64 cols))
// bids 128..255: dec tile  64x64 -> g_dph  (4m x 2n warps, 16 rows x 32 cols)
// Stage: A (<=256 rows x 80B) @0 | Bh 64x80B @20480 | Bl @25600 = 30720 x2.
// ---------------------------------------------------------------------------
#define PROJ_STAGE 30720
#define PROJ_SMEM (2 * PROJ_STAGE)

__global__ __launch_bounds__(256, 2) void proj_kernel(const float* __restrict__ b1) {
    extern __shared__ char smem[];
    uint32_t sb = smem_u32(smem);

    int tid = threadIdx.x, wid = tid >> 5, lane = tid & 31;
    int gq = lane >> 2, tg = lane & 3;

    int id = blockIdx.x;
    bool isdec = id >= 128;
    int lid2 = isdec ? id - 128 : id;
    int tile_m = lid2 >> 4, tile_n = lid2 & 15;
    int m0 = tile_m * (isdec ? 64 : 256), n0 = tile_n * 64;
    int arows = isdec ? 64 : 256;

    const char* Ah = (const char*)(isdec ? g_dech : g_ench);
    const char* Bh = (const char*)(g_w1t_hi + (isdec ? 1024 * 512 : 0));
    const char* Bl = (const char*)(g_w1t_lo + (isdec ? 1024 * 512 : 0));

    auto issue = [&](int kc) {
        char* base = smem + (kc & 1) * PROJ_STAGE;
        int aiters = arows / 64;              // 4 for enc, 1 for dec
        for (int it = 0; it < aiters; it++) {
            int i = tid + it * 256;
            int r = i >> 2, sg = i & 3;
            size_t gsrc = (size_t)(m0 + r) * 1024 + kc * 64 + sg * 16;
            cp16(base + r * 80 + sg * 16, Ah + gsrc);
        }
        {
            int r = tid >> 2, sg = tid & 3;   // 64 rows x 4 segs
            size_t gsrc = (size_t)(n0 + r) * 1024 + kc * 64 + sg * 16;
            cp16(base + 20480 + r * 80 + sg * 16, Bh + gsrc);
            cp16(base + 25600 + r * 80 + sg * 16, Bl + gsrc);
        }
    };

    issue(0);
    CP_COMMIT();

    if (!isdec) {
        // ---------------- enc: warp = 32 rows x 64 cols ----------------
        uint32_t aOff = (uint32_t)(wid * 32 + ((lane >> 3) & 1) * 8 + (lane & 7)) * 80
                      + ((lane >> 4) & 1) * 16;
        uint32_t bOff = (uint32_t)(((lane >> 4) & 1) * 8 + (lane & 7)) * 80
                      + ((lane >> 3) & 1) * 16;

        float c[2][8][4];
        #pragma unroll
        for (int i = 0; i < 2; i++)
            #pragma unroll
            for (int j = 0; j < 8; j++)
                #pragma unroll
                for (int q = 0; q < 4; q++) c[i][j][q] = 0.f;

        for (int kc = 0; kc < 16; kc++) {
            CP_WAIT0();
            __syncthreads();
            if (kc + 1 < 16) { issue(kc + 1); CP_COMMIT(); }
            uint32_t base = sb + (kc & 1) * PROJ_STAGE;

            #pragma unroll
            for (int ks = 0; ks < 2; ks++) {
                uint32_t ko = ks * 32;
                uint32_t aH[2][4];
                #pragma unroll
                for (int mt = 0; mt < 2; mt++)
                    ldsm4(aH[mt], base + aOff + mt * 1280 + ko);
                #pragma unroll
                for (int p = 0; p < 4; p++) {
                    uint32_t bh[4], bl[4];
                    ldsm4(bh, base + 20480 + bOff + p * 1280 + ko);
                    ldsm4(bl, base + 25600 + bOff + p * 1280 + ko);
                    #pragma unroll
                    for (int mt = 0; mt < 2; mt++) {
                        mma_f16(c[mt][2 * p],     aH[mt], &bh[0]);
                        mma_f16(c[mt][2 * p],     aH[mt], &bl[0]);
                        mma_f16(c[mt][2 * p + 1], aH[mt], &bh[2]);
                        mma_f16(c[mt][2 * p + 1], aH[mt], &bl[2]);
                    }
                }
            }
        }

        #pragma unroll
        for (int mt = 0; mt < 2; mt++)
            #pragma unroll
            for (int nb = 0; nb < 8; nb++) {
                int col = n0 + nb * 8 + tg * 2;
                int row = m0 + wid * 32 + mt * 16 + gq;
                *(float2*)(g_ep + (size_t)row * 1024 + col) =
                    make_float2(c[mt][nb][0], c[mt][nb][1]);
                *(float2*)(g_ep + (size_t)(row + 8) * 1024 + col) =
                    make_float2(c[mt][nb][2], c[mt][nb][3]);
            }
    } else {
        // ---------------- dec: 4m x 2n warps, 16 rows x 32 cols ----------------
        int warp_m = wid >> 1, warp_n = wid & 1;
        uint32_t aOff = (uint32_t)(warp_m * 16 + ((lane >> 3) & 1) * 8 + (lane & 7)) * 80
                      + ((lane >> 4) & 1) * 16;
        uint32_t bOff = (uint32_t)(warp_n * 32 + ((lane >> 4) & 1) * 8 + (lane & 7)) * 80
                      + ((lane >> 3) & 1) * 16;

        float c[4][4];
        #pragma unroll
        for (int j = 0; j < 4; j++)
            #pragma unroll
            for (int q = 0; q < 4; q++) c[j][q] = 0.f;

        for (int kc = 0; kc < 16; kc++) {
            CP_WAIT0();
            __syncthreads();
            if (kc + 1 < 16) { issue(kc + 1); CP_COMMIT(); }
            uint32_t base = sb + (kc & 1) * PROJ_STAGE;

            #pragma unroll
            for (int ks = 0; ks < 2; ks++) {
                uint32_t ko = ks * 32;
                uint32_t aH[4];
                ldsm4(aH, base + aOff + ko);
                #pragma unroll
                for (int p = 0; p < 2; p++) {
                    uint32_t bh[4], bl[4];
                    ldsm4(bh, base + 20480 + bOff + p * 1280 + ko);
                    ldsm4(bl, base + 25600 + bOff + p * 1280 + ko);
                    mma_f16(c[2 * p],     aH, &bh[0]);
                    mma_f16(c[2 * p],     aH, &bl[0]);
                    mma_f16(c[2 * p + 1], aH, &bh[2]);
                    mma_f16(c[2 * p + 1], aH, &bl[2]);
                }
            }
        }

        #pragma unroll
        for (int nb = 0; nb < 4; nb++) {
            int col = n0 + warp_n * 32 + nb * 8 + tg * 2;
            int row = m0 + warp_m * 16 + gq;
            float bb0 = __ldg(b1 + col), bb1 = __ldg(b1 + col + 1);
            __half2 h0 = __floats2half2_rn(c[nb][0] + bb0, c[nb][1] + bb1);
            __half2 h1 = __floats2half2_rn(c[nb][2] + bb0, c[nb][3] + bb1);
            *(__half2*)(g_dph + (size_t)row * 1024 + col) = h0;
            *(__half2*)(g_dph + (size_t)(row + 8) * 1024 + col) = h1;
        }
    }
}

// ---------------------------------------------------------------------------
// Fused kernel: CTA = (batch b, 2 t, 64 u) -> M=128 x N=128, K=1024/64.
// Warps 4m x 2n, mt=2.  Software-pipelined at k-step granularity: B-frags and
// A-frags (tanh(ep+dp)) for ks+1 are loaded/generated BEFORE MMAs of ks, so
// the tensor pipe never waits on just-issued loads.
// smem: Bs 2x[128][72]h (36864) | dps 2x[64][72]h (18432) | sep [2][1024]f (8192)
// ---------------------------------------------------------------------------
#define FB_BS    0
#define FB_DPS   36864
#define FB_SEP   55296
#define FUSED_SMEM (55296 + 8192)

__global__ __launch_bounds__(256, 2) void fused_kernel(float* __restrict__ out,
                                                       const float* __restrict__ b2) {
    extern __shared__ char smem[];
    __half* Bs  = (__half*)(smem + FB_BS);     // [2][128][72]
    __half* dps = (__half*)(smem + FB_DPS);    // [2][64][72]
    float*  sep = (float*)(smem + FB_SEP);     // [2][1024]

    int tid = threadIdx.x, wid = tid >> 5, lane = tid & 31;
    int gq = lane >> 2, tg = lane & 3;
    int warp_m = wid >> 1, warp_n = wid & 1;

    int b  = blockIdx.x >> 7;
    int tp = blockIdx.x & 127;
    int t0 = tp * 2;

    // stage ep (2 x 1024 f32) once
    #pragma unroll
    for (int it = 0; it < 2; it++) {
        int i = tid + it * 256;
        int r = i >> 8, k = (i & 255) * 4;
        *(float4*)&sep[r * 1024 + k] =
            *(const float4*)(g_ep + (size_t)(b * 256 + t0 + r) * 1024 + k);
    }

    auto issue = [&](int kc) {
        int buf = kc & 1;
        #pragma unroll
        for (int it = 0; it < 4; it++) {     // Bs: 1024 segs of 16B
            int i = tid + it * 256;
            int r = i >> 3, sg = i & 7;
            cp16((char*)Bs + buf * 18432 + r * 144 + sg * 16,
                 (const char*)g_w2t + (size_t)r * 2048 + kc * 128 + sg * 16);
        }
        #pragma unroll
        for (int it = 0; it < 2; it++) {     // dps fp16: 512 segs of 16B
            int i = tid + it * 256;
            int u = i >> 3, sg = i & 7;
            cp16((char*)dps + buf * 9216 + u * 144 + sg * 16,
                 (const char*)g_dph + (size_t)(b * 64 + u) * 2048 + kc * 128 + sg * 16);
        }
    };

    int tl = warp_m >> 1;                 // t_local of this warp's rows
    int ub = (warp_m & 1) * 32;           // u base of this warp's rows

    uint32_t BsAddr = smem_u32(Bs);
    uint32_t bLane = (uint32_t)(((lane >> 4) & 1) * 8 + (lane & 7)) * 144
                   + ((lane >> 3) & 1) * 16;
    uint32_t baddr[4];
    #pragma unroll
    for (int p = 0; p < 4; p++)
        baddr[p] = BsAddr + (uint32_t)(warp_n * 64 + p * 16) * 144 + bLane;

    float c[2][8][4];
    #pragma unroll
    for (int i = 0; i < 2; i++)
        #pragma unroll
        for (int j = 0; j < 8; j++)
            #pragma unroll
            for (int q = 0; q < 4; q++) c[i][j][q] = 0.f;

    issue(0);
    CP_COMMIT();

    for (int kc = 0; kc < 16; kc++) {
        CP_WAIT0();
        __syncthreads();
        if (kc + 1 < 16) { issue(kc + 1); CP_COMMIT(); }

        int buf = kc & 1;
        const float*  ept = sep + tl * 1024 + kc * 64;
        const __half* dph = dps + buf * 4608;
        uint32_t bufoff = (uint32_t)buf * 18432;

        uint32_t br[2][16];
        uint32_t areg[2][2][4];

        auto genA = [&](uint32_t (*ar)[4], int ks) {
            #pragma unroll
            for (int kp = 0; kp < 2; kp++) {
                int k = ks * 16 + tg * 2 + kp * 8;
                float2 e = *(const float2*)(ept + k);
                #pragma unroll
                for (int mt = 0; mt < 2; mt++) {
                    int u = ub + mt * 16 + gq;
                    __half2 da = *(const __half2*)(dph + u * 72 + k);
                    __half2 db = *(const __half2*)(dph + (u + 8) * 72 + k);
                    float2 fa = __half22float2(da);
                    float2 fb = __half22float2(db);
                    __half2 ha = __floats2half2_rn(e.x + fa.x, e.y + fa.y);
                    __half2 hb = __floats2half2_rn(e.x + fb.x, e.y + fb.y);
                    ar[mt][kp * 2 + 0] = tanh2_fast(*(uint32_t*)&ha);
                    ar[mt][kp * 2 + 1] = tanh2_fast(*(uint32_t*)&hb);
                }
            }
        };

        // prologue: frags for ks=0
        #pragma unroll
        for (int p = 0; p < 4; p++) ldsm4(&br[0][p * 4], baddr[p] + bufoff);
        genA(areg[0], 0);

        #pragma unroll
        for (int ks = 0; ks < 4; ks++) {
            int cur = ks & 1, nxt = cur ^ 1;
            if (ks < 3) {
                #pragma unroll
                for (int p = 0; p < 4; p++)
                    ldsm4(&br[nxt][p * 4], baddr[p] + bufoff + (ks + 1) * 32);
                genA(areg[nxt], ks + 1);
            }
            #pragma unroll
            for (int p = 0; p < 4; p++) {
                mma_f16(c[0][2 * p],     areg[cur][0], &br[cur][p * 4 + 0]);
                mma_f16(c[0][2 * p + 1], areg[cur][0], &br[cur][p * 4 + 2]);
                mma_f16(c[1][2 * p],     areg[cur][1], &br[cur][p * 4 + 0]);
                mma_f16(c[1][2 * p + 1], areg[cur][1], &br[cur][p * 4 + 2]);
            }
        }
    }

    // epilogue: global row = b*16384 + t0*64 + local (contiguous 128 rows)
    size_t orow0 = (size_t)b * 16384 + (size_t)t0 * 64;
    #pragma unroll
    for (int mt = 0; mt < 2; mt++) {
        int row0 = warp_m * 32 + mt * 16 + gq;
        #pragma unroll
        for (int nb = 0; nb < 8; nb++) {
            int col = warp_n * 64 + nb * 8 + tg * 2;
            float bb0 = __ldg(b2 + col);
            float bb1 = __ldg(b2 + col + 1);
            float2 v0 = make_float2(c[mt][nb][0] + bb0, c[mt][nb][1] + bb1);
            float2 v1 = make_float2(c[mt][nb][2] + bb0, c[mt][nb][3] + bb1);
            *(float2*)(out + (orow0 + row0) * 128 + col) = v0;
            *(float2*)(out + (orow0 + row0 + 8) * 128 + col) = v1;
        }
    }
}

// ---------------------------------------------------------------------------
extern "C" void kernel_launch(void* const* d_in, const int* in_sizes, int n_in,
                              void* d_out, int out_size) {
    const float* enc = (const float*)d_in[0];
    const float* dec = (const float*)d_in[1];
    const float* W1  = (const float*)d_in[2];
    const float* b1  = (const float*)d_in[3];
    const float* W2  = (const float*)d_in[4];
    const float* b2  = (const float*)d_in[5];
    float* out = (float*)d_out;

    cudaFuncSetAttribute(proj_kernel,  cudaFuncAttributeMaxDynamicSharedMemorySize, PROJ_SMEM);
    cudaFuncSetAttribute(fused_kernel, cudaFuncAttributeMaxDynamicSharedMemorySize, FUSED_SMEM);

    prep_all<<<2176, 256>>>(enc, dec, W1, W2);
    proj_kernel<<<256, 256, PROJ_SMEM>>>(b1);
    fused_kernel<<<1024, 256, FUSED_SMEM>>>(out, b2);
}